// round 2
// baseline (speedup 1.0000x reference)
#include <cuda_runtime.h>

// ---------------- problem constants (fixed shapes) ----------------
constexpr int cN = 100000;   // nodes
constexpr int cE = 1600000;  // edges
constexpr int cD = 128;      // feature dim
constexpr int cK = 4;        // etypes
constexpr int cG = 128;      // gather dim
constexpr int cTD = 3 * cD;  // 384

constexpr int cM = cK * cN;          // 400000 keys (dst*4+etype)
constexpr int SCAN_NB = (cM + 1023) / 1024;  // 391

// ---------------- scratch (static __device__ — no allocs allowed) ----------------
__device__ __align__(16) float g_h0[(size_t)cN * cD];
__device__ __align__(16) float g_h1[(size_t)cN * cD];
__device__ __align__(16) float g_s[(size_t)cK * cN * cD];   // per-(etype,node) aggregated h
__device__ __align__(16) float g_a[(size_t)cN * cD];        // message result / jlin scratch
__device__ __align__(16) float g_gi[(size_t)cN * cTD];
__device__ __align__(16) float g_gh[(size_t)cN * cTD];
__device__ __align__(16) float g_gate[(size_t)cN * cG];

__device__ int g_deg[cM];
__device__ int g_rp[cM + 1];
__device__ int g_cur[cM];
__device__ int g_esrc[cE];
__device__ int g_part[512];

// ---------------- helpers ----------------
__device__ __forceinline__ void ffma2(unsigned long long& c, unsigned long long a,
                                      unsigned long long b) {
    asm("fma.rn.f32x2 %0, %1, %2, %0;" : "+l"(c) : "l"(a), "l"(b));
}
__device__ __forceinline__ float f2lo(unsigned long long v) {
    return __uint_as_float((unsigned int)(v & 0xffffffffull));
}
__device__ __forceinline__ float f2hi(unsigned long long v) {
    return __uint_as_float((unsigned int)(v >> 32));
}
__device__ __forceinline__ float sigmf(float x) { return 1.0f / (1.0f + __expf(-x)); }

// ---------------- CSR build ----------------
__global__ void k_fill_deg() {
    int i = blockIdx.x * blockDim.x + threadIdx.x;
    if (i < cM) g_deg[i] = 0;
}

__global__ void k_hist(const int* __restrict__ dst, const int* __restrict__ et) {
    int e = blockIdx.x * blockDim.x + threadIdx.x;
    if (e < cE) atomicAdd(&g_deg[dst[e] * 4 + et[e]], 1);
}

__global__ void k_scan1() {  // 391 blocks x 1024 threads: per-block exclusive scan of g_deg -> g_rp
    __shared__ int sm[1024];
    int i = blockIdx.x * 1024 + threadIdx.x;
    int v = (i < cM) ? g_deg[i] : 0;
    sm[threadIdx.x] = v;
    __syncthreads();
    for (int off = 1; off < 1024; off <<= 1) {
        int t = 0;
        if (threadIdx.x >= off) t = sm[threadIdx.x - off];
        __syncthreads();
        sm[threadIdx.x] += t;
        __syncthreads();
    }
    if (i < cM) g_rp[i] = sm[threadIdx.x] - v;  // exclusive
    if (threadIdx.x == 1023) g_part[blockIdx.x] = sm[1023];
}

__global__ void k_scan2() {  // 1 block x 512: exclusive scan of block partials
    __shared__ int sm[512];
    int t = threadIdx.x;
    int v = (t < SCAN_NB) ? g_part[t] : 0;
    sm[t] = v;
    __syncthreads();
    for (int off = 1; off < 512; off <<= 1) {
        int x = 0;
        if (t >= off) x = sm[t - off];
        __syncthreads();
        sm[t] += x;
        __syncthreads();
    }
    if (t < SCAN_NB) g_part[t] = sm[t] - v;  // exclusive
    if (t == 511) g_rp[cM] = sm[511];        // total (== cE)
}

__global__ void k_scan3() {
    int i = blockIdx.x * 1024 + threadIdx.x;
    if (i < cM) g_rp[i] += g_part[blockIdx.x];
}

__global__ void k_copy_cur() {
    int i = blockIdx.x * blockDim.x + threadIdx.x;
    if (i < cM) g_cur[i] = g_rp[i];
}

__global__ void k_scatter(const int* __restrict__ src, const int* __restrict__ dst,
                          const int* __restrict__ et) {
    int e = blockIdx.x * blockDim.x + threadIdx.x;
    if (e < cE) {
        int key = dst[e] * 4 + et[e];
        int pos = atomicAdd(&g_cur[key], 1);
        g_esrc[pos] = src[e];
    }
}

// ---------------- per-step aggregation: s[k][v] = sum_{edges of type k into v} h[src] ----------------
__global__ void k_agg(const float* __restrict__ h) {
    int warp = (blockIdx.x * blockDim.x + threadIdx.x) >> 5;
    int lane = threadIdx.x & 31;
    if (warp >= cN) return;
    const float4* hp = reinterpret_cast<const float4*>(h);
    float4* sp = reinterpret_cast<float4*>(g_s);
    int base = warp * 4;
    int r0 = g_rp[base];
#pragma unroll
    for (int k = 0; k < cK; k++) {
        int r1 = g_rp[base + k + 1];
        float4 acc = make_float4(0.f, 0.f, 0.f, 0.f);
        for (int i = r0; i < r1; i++) {
            int s = __ldg(&g_esrc[i]);
            float4 x = hp[(size_t)s * 32 + lane];
            acc.x += x.x; acc.y += x.y; acc.z += x.z; acc.w += x.w;
        }
        sp[((size_t)k * cN + warp) * 32 + lane] = acc;
        r0 = r1;
    }
}

// ---------------- generic SGEMM: Y[r, colBase+n] = X[r,:128] . W[colBase+n, :128] (+bias)(+=Y) ----------------
constexpr int BM = 128, BN = 64, LDT = 132;
constexpr int SMEM_BYTES = (BM + BN) * LDT * 4;  // 101376

__global__ void sgemm128(const float* __restrict__ X, const float* __restrict__ W, int ldw,
                         const float* __restrict__ bias, float* __restrict__ Y, int ldy,
                         int nrows, int accumulate) {
    extern __shared__ float smn[];
    float* Xs = smn;             // [128][132]
    float* Ws = smn + BM * LDT;  // [64][132]
    int tid = threadIdx.x;
    int tm = tid & 15, tn = tid >> 4;
    int rowBase = blockIdx.x * BM, colBase = blockIdx.y * BN;

    for (int idx = tid; idx < BM * 32; idx += 256) {
        int row = idx >> 5, c4 = idx & 31;
        float4 v = make_float4(0.f, 0.f, 0.f, 0.f);
        int r = rowBase + row;
        if (r < nrows) v = *reinterpret_cast<const float4*>(X + (size_t)r * cD + c4 * 4);
        *reinterpret_cast<float4*>(Xs + row * LDT + c4 * 4) = v;
    }
    for (int idx = tid; idx < BN * 32; idx += 256) {
        int o = idx >> 5, c4 = idx & 31;
        float4 v = *reinterpret_cast<const float4*>(W + (size_t)(colBase + o) * ldw + c4 * 4);
        *reinterpret_cast<float4*>(Ws + o * LDT + c4 * 4) = v;
    }
    __syncthreads();

    unsigned long long c2[8][4];
#pragma unroll
    for (int i = 0; i < 8; i++)
#pragma unroll
        for (int j = 0; j < 4; j++) c2[i][j] = 0ull;

#pragma unroll 4
    for (int kk = 0; kk < cD; kk += 2) {
        unsigned long long a[8], b[4];
#pragma unroll
        for (int i = 0; i < 8; i++)
            a[i] = *reinterpret_cast<const unsigned long long*>(Xs + (tm + i * 16) * LDT + kk);
#pragma unroll
        for (int j = 0; j < 4; j++)
            b[j] = *reinterpret_cast<const unsigned long long*>(Ws + (tn * 4 + j) * LDT + kk);
#pragma unroll
        for (int i = 0; i < 8; i++)
#pragma unroll
            for (int j = 0; j < 4; j++) ffma2(c2[i][j], a[i], b[j]);
    }

#pragma unroll
    for (int i = 0; i < 8; i++) {
        int r = rowBase + tm + i * 16;
        if (r >= nrows) continue;
        float4 o;
        float* op = &o.x;
#pragma unroll
        for (int j = 0; j < 4; j++) {
            float v = f2lo(c2[i][j]) + f2hi(c2[i][j]);
            if (bias) v += __ldg(&bias[colBase + tn * 4 + j]);
            op[j] = v;
        }
        float* yp = Y + (size_t)r * ldy + colBase + tn * 4;
        if (accumulate) {
            float4 old = *reinterpret_cast<float4*>(yp);
            o.x += old.x; o.y += old.y; o.z += old.z; o.w += old.w;
        }
        *reinterpret_cast<float4*>(yp) = o;
    }
}

// ---------------- etype GEMM: a[v] = sum_k s_k[v] @ W_k^T + sum_k cnt_k(v) * b_k ----------------
__global__ void sgemm_etype(const float* __restrict__ Wet, const float* __restrict__ bet) {
    extern __shared__ float smn[];
    float* Xs = smn;
    float* Ws = smn + BM * LDT;
    int tid = threadIdx.x;
    int tm = tid & 15, tn = tid >> 4;
    int rowBase = blockIdx.x * BM, colBase = blockIdx.y * BN;

    unsigned long long c2[8][4];
#pragma unroll
    for (int i = 0; i < 8; i++)
#pragma unroll
        for (int j = 0; j < 4; j++) c2[i][j] = 0ull;

    for (int ke = 0; ke < cK; ke++) {
        if (ke) __syncthreads();
        const float* Sk = g_s + (size_t)ke * cN * cD;
        const float* Wk = Wet + (size_t)ke * cD * cD;
        for (int idx = tid; idx < BM * 32; idx += 256) {
            int row = idx >> 5, c4 = idx & 31;
            float4 v = make_float4(0.f, 0.f, 0.f, 0.f);
            int r = rowBase + row;
            if (r < cN) v = *reinterpret_cast<const float4*>(Sk + (size_t)r * cD + c4 * 4);
            *reinterpret_cast<float4*>(Xs + row * LDT + c4 * 4) = v;
        }
        for (int idx = tid; idx < BN * 32; idx += 256) {
            int o = idx >> 5, c4 = idx & 31;
            float4 v = *reinterpret_cast<const float4*>(Wk + (size_t)(colBase + o) * cD + c4 * 4);
            *reinterpret_cast<float4*>(Ws + o * LDT + c4 * 4) = v;
        }
        __syncthreads();
#pragma unroll 4
        for (int kk = 0; kk < cD; kk += 2) {
            unsigned long long a[8], b[4];
#pragma unroll
            for (int i = 0; i < 8; i++)
                a[i] = *reinterpret_cast<const unsigned long long*>(Xs + (tm + i * 16) * LDT + kk);
#pragma unroll
            for (int j = 0; j < 4; j++)
                b[j] = *reinterpret_cast<const unsigned long long*>(Ws + (tn * 4 + j) * LDT + kk);
#pragma unroll
            for (int i = 0; i < 8; i++)
#pragma unroll
                for (int j = 0; j < 4; j++) ffma2(c2[i][j], a[i], b[j]);
        }
    }

#pragma unroll
    for (int i = 0; i < 8; i++) {
        int r = rowBase + tm + i * 16;
        if (r >= cN) continue;
        int rpv[5];
#pragma unroll
        for (int k = 0; k <= 4; k++) rpv[k] = g_rp[4 * r + k];
        float cnt[4];
#pragma unroll
        for (int k = 0; k < 4; k++) cnt[k] = (float)(rpv[k + 1] - rpv[k]);
        float4 o;
        float* op = &o.x;
#pragma unroll
        for (int j = 0; j < 4; j++) {
            int col = colBase + tn * 4 + j;
            float v = f2lo(c2[i][j]) + f2hi(c2[i][j]);
#pragma unroll
            for (int k = 0; k < 4; k++) v += cnt[k] * __ldg(&bet[k * cD + col]);
            op[j] = v;
        }
        *reinterpret_cast<float4*>(g_a + (size_t)r * cD + colBase + tn * 4) = o;
    }
}

// ---------------- GRU elementwise ----------------
__global__ void k_gru(const float* __restrict__ h, float* __restrict__ hout) {
    int idx = blockIdx.x * blockDim.x + threadIdx.x;
    if (idx >= cN * cD) return;
    int n = idx >> 7, d = idx & 127;
    size_t b3 = (size_t)n * cTD + d;
    float ir = g_gi[b3], iz = g_gi[b3 + 128], inn = g_gi[b3 + 256];
    float hr = g_gh[b3], hz = g_gh[b3 + 128], hn = g_gh[b3 + 256];
    float r = sigmf(ir + hr);
    float z = sigmf(iz + hz);
    float nn = tanhf(inn + r * hn);
    hout[idx] = (1.0f - z) * nn + z * h[idx];
}

// ---------------- final combine: out = sigmoid(gate_pre) * jlin ----------------
__global__ void k_combine(float* __restrict__ out) {
    int idx = blockIdx.x * blockDim.x + threadIdx.x;
    if (idx >= cN * cG) return;
    out[idx] = sigmf(g_gate[idx]) * g_a[idx];
}

// ---------------- host ----------------
extern "C" void kernel_launch(void* const* d_in, const int* in_sizes, int n_in,
                              void* d_out, int out_size) {
    (void)in_sizes; (void)n_in; (void)out_size;
    const float* features = (const float*)d_in[0];
    const int*   src      = (const int*)d_in[1];
    const int*   dst      = (const int*)d_in[2];
    const int*   etypes   = (const int*)d_in[3];
    const float* W_et     = (const float*)d_in[4];
    const float* b_et     = (const float*)d_in[5];
    const float* W_ih     = (const float*)d_in[6];
    const float* b_ih     = (const float*)d_in[7];
    const float* W_hh     = (const float*)d_in[8];
    const float* b_hh     = (const float*)d_in[9];
    const float* i_w      = (const float*)d_in[10];
    const float* i_b      = (const float*)d_in[11];
    const float* j_w      = (const float*)d_in[12];
    const float* j_b      = (const float*)d_in[13];
    float* out = (float*)d_out;

    float *h0, *h1, *abuf, *gi, *gh, *gate;
    cudaGetSymbolAddress((void**)&h0, g_h0);
    cudaGetSymbolAddress((void**)&h1, g_h1);
    cudaGetSymbolAddress((void**)&abuf, g_a);
    cudaGetSymbolAddress((void**)&gi, g_gi);
    cudaGetSymbolAddress((void**)&gh, g_gh);
    cudaGetSymbolAddress((void**)&gate, g_gate);

    cudaFuncSetAttribute(sgemm128, cudaFuncAttributeMaxDynamicSharedMemorySize, SMEM_BYTES);
    cudaFuncSetAttribute(sgemm_etype, cudaFuncAttributeMaxDynamicSharedMemorySize, SMEM_BYTES);

    // ---- CSR build (sorted by dst*4+etype) ----
    k_fill_deg<<<(cM + 255) / 256, 256>>>();
    k_hist<<<(cE + 255) / 256, 256>>>(dst, etypes);
    k_scan1<<<SCAN_NB, 1024>>>();
    k_scan2<<<1, 512>>>();
    k_scan3<<<SCAN_NB, 1024>>>();
    k_copy_cur<<<(cM + 255) / 256, 256>>>();
    k_scatter<<<(cE + 255) / 256, 256>>>(src, dst, etypes);

    const int RB = (cN + BM - 1) / BM;  // 782 row tiles
    dim3 gA(RB, cD / BN);               // 128 output cols
    dim3 gG(RB, cTD / BN);              // 384 output cols

    const float* hc = features;
    float* houts[3] = {h0, h1, h0};
    for (int s = 0; s < 3; s++) {
        k_agg<<<(cN + 7) / 8, 256>>>(hc);
        sgemm_etype<<<gA, 256, SMEM_BYTES>>>(W_et, b_et);                        // -> g_a
        sgemm128<<<gG, 256, SMEM_BYTES>>>(abuf, W_ih, cD, b_ih, gi, cTD, cN, 0); // gi
        sgemm128<<<gG, 256, SMEM_BYTES>>>(hc,   W_hh, cD, b_hh, gh, cTD, cN, 0); // gh
        k_gru<<<(cN * cD + 255) / 256, 256>>>(hc, houts[s]);
        hc = houts[s];
    }

    // gated output head
    sgemm128<<<gA, 256, SMEM_BYTES>>>(hc, i_w, 2 * cD, nullptr, gate, cG, cN, 0);
    sgemm128<<<gA, 256, SMEM_BYTES>>>(features, i_w + cD, 2 * cD, i_b, gate, cG, cN, 1);
    sgemm128<<<gA, 256, SMEM_BYTES>>>(hc, j_w, cD, j_b, abuf, cG, cN, 0);  // jlin -> g_a
    k_combine<<<(cN * cG + 255) / 256, 256>>>(out);
}

// round 3
// speedup vs baseline: 1.3687x; 1.3687x over previous
#include <cuda_runtime.h>
#include <cstdint>

// ---------------- problem constants (fixed shapes) ----------------
constexpr int cN = 100000;   // nodes
constexpr int cE = 1600000;  // edges
constexpr int cD = 128;      // feature dim
constexpr int cK = 4;        // etypes
constexpr int cG = 128;      // gather dim
constexpr int cTD = 3 * cD;  // 384

constexpr int cM = cK * cN;                  // 400000 keys (dst*4+etype)
constexpr int SCAN_NB = (cM + 1023) / 1024;  // 391

// ---------------- scratch (static __device__ — no allocs allowed) ----------------
__device__ __align__(16) float g_h0[(size_t)cN * cD];
__device__ __align__(16) float g_h1[(size_t)cN * cD];
__device__ __align__(16) float g_s[(size_t)cK * cN * cD];   // per-(etype,node) aggregated h
__device__ __align__(16) float g_a[(size_t)cN * cD];        // message result / jlin scratch
__device__ __align__(16) float g_gi[(size_t)cN * cTD];
__device__ __align__(16) float g_gh[(size_t)cN * cTD];
__device__ __align__(16) float g_gate[(size_t)cN * cG];
__device__ __align__(16) float g_bsum[(size_t)cN * cD];     // sum_k cnt_k(v) * b_et[k]

__device__ int g_deg[cM];
__device__ int g_rp[cM + 1];
__device__ int g_cur[cM];
__device__ int g_esrc[cE];
__device__ int g_part[512];

// ---------------- helpers ----------------
__device__ __forceinline__ float sigmf(float x) { return 1.0f / (1.0f + __expf(-x)); }

__device__ __forceinline__ uint32_t f2tf(float x) {
    uint32_t r;
    asm("cvt.rna.tf32.f32 %0, %1;" : "=r"(r) : "f"(x));
    return r;
}

__device__ __forceinline__ void mma_tf32(float c[4], const uint32_t a[4], const uint32_t b[2]) {
    asm volatile(
        "mma.sync.aligned.m16n8k8.row.col.f32.tf32.tf32.f32 "
        "{%0,%1,%2,%3}, {%4,%5,%6,%7}, {%8,%9}, {%0,%1,%2,%3};"
        : "+f"(c[0]), "+f"(c[1]), "+f"(c[2]), "+f"(c[3])
        : "r"(a[0]), "r"(a[1]), "r"(a[2]), "r"(a[3]), "r"(b[0]), "r"(b[1]));
}

// ---------------- CSR build ----------------
__global__ void k_fill_deg() {
    int i = blockIdx.x * blockDim.x + threadIdx.x;
    if (i < cM) g_deg[i] = 0;
}

__global__ void k_hist(const int* __restrict__ dst, const int* __restrict__ et) {
    int e = blockIdx.x * blockDim.x + threadIdx.x;
    if (e < cE) atomicAdd(&g_deg[dst[e] * 4 + et[e]], 1);
}

__global__ void k_scan1() {
    __shared__ int sm[1024];
    int i = blockIdx.x * 1024 + threadIdx.x;
    int v = (i < cM) ? g_deg[i] : 0;
    sm[threadIdx.x] = v;
    __syncthreads();
    for (int off = 1; off < 1024; off <<= 1) {
        int t = 0;
        if (threadIdx.x >= off) t = sm[threadIdx.x - off];
        __syncthreads();
        sm[threadIdx.x] += t;
        __syncthreads();
    }
    if (i < cM) g_rp[i] = sm[threadIdx.x] - v;  // exclusive
    if (threadIdx.x == 1023) g_part[blockIdx.x] = sm[1023];
}

__global__ void k_scan2() {
    __shared__ int sm[512];
    int t = threadIdx.x;
    int v = (t < SCAN_NB) ? g_part[t] : 0;
    sm[t] = v;
    __syncthreads();
    for (int off = 1; off < 512; off <<= 1) {
        int x = 0;
        if (t >= off) x = sm[t - off];
        __syncthreads();
        sm[t] += x;
        __syncthreads();
    }
    if (t < SCAN_NB) g_part[t] = sm[t] - v;  // exclusive
    if (t == 511) g_rp[cM] = sm[511];
}

__global__ void k_scan3() {
    int i = blockIdx.x * 1024 + threadIdx.x;
    if (i < cM) g_rp[i] += g_part[blockIdx.x];
}

__global__ void k_copy_cur() {
    int i = blockIdx.x * blockDim.x + threadIdx.x;
    if (i < cM) g_cur[i] = g_rp[i];
}

__global__ void k_scatter(const int* __restrict__ src, const int* __restrict__ dst,
                          const int* __restrict__ et) {
    int e = blockIdx.x * blockDim.x + threadIdx.x;
    if (e < cE) {
        int key = dst[e] * 4 + et[e];
        int pos = atomicAdd(&g_cur[key], 1);
        g_esrc[pos] = src[e];
    }
}

// ---------------- precompute per-node etype-bias sum (constant across steps) ----------------
__global__ void k_bsum(const float* __restrict__ bet) {
    int idx = blockIdx.x * blockDim.x + threadIdx.x;
    if (idx >= cN * cD) return;
    int r = idx >> 7, col = idx & 127;
    int rp[5];
#pragma unroll
    for (int k = 0; k <= 4; k++) rp[k] = g_rp[4 * r + k];
    float v = 0.f;
#pragma unroll
    for (int k = 0; k < 4; k++) v += (float)(rp[k + 1] - rp[k]) * __ldg(&bet[k * cD + col]);
    g_bsum[idx] = v;
}

// ---------------- per-step aggregation: s[k][v] = sum_{edges of type k into v} h[src] ----------------
__global__ void k_agg(const float* __restrict__ h) {
    int warp = (blockIdx.x * blockDim.x + threadIdx.x) >> 5;
    int lane = threadIdx.x & 31;
    if (warp >= cN) return;
    const float4* hp = reinterpret_cast<const float4*>(h);
    float4* sp = reinterpret_cast<float4*>(g_s);
    int base = warp * 4;
    int r0 = g_rp[base];
#pragma unroll
    for (int k = 0; k < cK; k++) {
        int r1 = g_rp[base + k + 1];
        float4 acc = make_float4(0.f, 0.f, 0.f, 0.f);
        for (int i = r0; i < r1; i++) {
            int s = __ldg(&g_esrc[i]);
            float4 x = hp[(size_t)s * 32 + lane];
            acc.x += x.x; acc.y += x.y; acc.z += x.z; acc.w += x.w;
        }
        sp[((size_t)k * cN + warp) * 32 + lane] = acc;
        r0 = r1;
    }
}

// ---------------- TF32 tensor-core GEMM: Y[r, colBase+n] = X[r,:128] . W[n,:128] ----------------
constexpr int BM = 128, BN = 64, LDT = 132;
constexpr int SMEM_BYTES = (BM + BN) * LDT * 4;  // 101376

// copy helpers: load fp32 tile rows into smem with tf32 rounding applied
__device__ __forceinline__ void load_tile_X(const float* __restrict__ X, float* Xs,
                                            int rowBase, int nrows, int tid) {
    for (int idx = tid; idx < BM * 32; idx += 256) {
        int row = idx >> 5, c4 = idx & 31;
        float4 v = make_float4(0.f, 0.f, 0.f, 0.f);
        int r = rowBase + row;
        if (r < nrows) v = *reinterpret_cast<const float4*>(X + (size_t)r * cD + c4 * 4);
        uint32_t* d = reinterpret_cast<uint32_t*>(Xs + row * LDT + c4 * 4);
        d[0] = f2tf(v.x); d[1] = f2tf(v.y); d[2] = f2tf(v.z); d[3] = f2tf(v.w);
    }
}
__device__ __forceinline__ void load_tile_W(const float* __restrict__ W, int ldw, float* Ws,
                                            int colBase, int tid) {
    for (int idx = tid; idx < BN * 32; idx += 256) {
        int o = idx >> 5, c4 = idx & 31;
        float4 v = *reinterpret_cast<const float4*>(W + (size_t)(colBase + o) * ldw + c4 * 4);
        uint32_t* d = reinterpret_cast<uint32_t*>(Ws + o * LDT + c4 * 4);
        d[0] = f2tf(v.x); d[1] = f2tf(v.y); d[2] = f2tf(v.z); d[3] = f2tf(v.w);
    }
}

// core compute over the staged K=128 tiles: c[2][4][4] per thread
__device__ __forceinline__ void mma_mainloop(const float* Xs, const float* Ws,
                                             int wm, int wn, int gr, int gc,
                                             float c[2][4][4]) {
#pragma unroll
    for (int k0 = 0; k0 < cD; k0 += 8) {
        uint32_t a[2][4], b[4][2];
#pragma unroll
        for (int i = 0; i < 2; i++) {
            const float* base = Xs + (wm + i * 16 + gr) * LDT + k0 + gc;
            a[i][0] = __float_as_uint(base[0]);
            a[i][1] = __float_as_uint(base[8 * LDT]);
            a[i][2] = __float_as_uint(base[4]);
            a[i][3] = __float_as_uint(base[8 * LDT + 4]);
        }
#pragma unroll
        for (int j = 0; j < 4; j++) {
            const float* base = Ws + (wn + j * 8 + gr) * LDT + k0 + gc;
            b[j][0] = __float_as_uint(base[0]);
            b[j][1] = __float_as_uint(base[4]);
        }
#pragma unroll
        for (int i = 0; i < 2; i++)
#pragma unroll
            for (int j = 0; j < 4; j++) mma_tf32(c[i][j], a[i], b[j]);
    }
}

__global__ void sgemm_tf32(const float* __restrict__ X, const float* __restrict__ W, int ldw,
                           const float* __restrict__ bias, float* __restrict__ Y, int ldy,
                           int nrows, int accumulate) {
    extern __shared__ float smn[];
    float* Xs = smn;
    float* Ws = smn + BM * LDT;
    int tid = threadIdx.x;
    int rowBase = blockIdx.x * BM, colBase = blockIdx.y * BN;

    load_tile_X(X, Xs, rowBase, nrows, tid);
    load_tile_W(W, ldw, Ws, colBase, tid);
    __syncthreads();

    int lane = tid & 31, warp = tid >> 5;
    int wm = (warp & 3) * 32, wn = (warp >> 2) * 32;
    int gr = lane >> 2, gc = lane & 3;

    float c[2][4][4];
#pragma unroll
    for (int i = 0; i < 2; i++)
#pragma unroll
        for (int j = 0; j < 4; j++)
#pragma unroll
            for (int q = 0; q < 4; q++) c[i][j][q] = 0.f;

    mma_mainloop(Xs, Ws, wm, wn, gr, gc, c);

#pragma unroll
    for (int i = 0; i < 2; i++) {
#pragma unroll
        for (int j = 0; j < 4; j++) {
            int col = colBase + wn + j * 8 + 2 * gc;
            float b0 = 0.f, b1 = 0.f;
            if (bias) { b0 = __ldg(&bias[col]); b1 = __ldg(&bias[col + 1]); }
#pragma unroll
            for (int half = 0; half < 2; half++) {
                int r = rowBase + wm + i * 16 + gr + half * 8;
                if (r >= nrows) continue;
                float2 o = make_float2(c[i][j][half * 2] + b0, c[i][j][half * 2 + 1] + b1);
                float* yp = Y + (size_t)r * ldy + col;
                if (accumulate) {
                    float2 old = *reinterpret_cast<float2*>(yp);
                    o.x += old.x; o.y += old.y;
                }
                *reinterpret_cast<float2*>(yp) = o;
            }
        }
    }
}

// ---------------- etype GEMM: a[v] = sum_k s_k[v] @ W_k^T + g_bsum[v] ----------------
__global__ void sgemm_etype_tf32(const float* __restrict__ Wet) {
    extern __shared__ float smn[];
    float* Xs = smn;
    float* Ws = smn + BM * LDT;
    int tid = threadIdx.x;
    int rowBase = blockIdx.x * BM, colBase = blockIdx.y * BN;

    int lane = tid & 31, warp = tid >> 5;
    int wm = (warp & 3) * 32, wn = (warp >> 2) * 32;
    int gr = lane >> 2, gc = lane & 3;

    float c[2][4][4];
#pragma unroll
    for (int i = 0; i < 2; i++)
#pragma unroll
        for (int j = 0; j < 4; j++)
#pragma unroll
            for (int q = 0; q < 4; q++) c[i][j][q] = 0.f;

    for (int ke = 0; ke < cK; ke++) {
        if (ke) __syncthreads();
        load_tile_X(g_s + (size_t)ke * cN * cD, Xs, rowBase, cN, tid);
        load_tile_W(Wet + (size_t)ke * cD * cD, cD, Ws, colBase, tid);
        __syncthreads();
        mma_mainloop(Xs, Ws, wm, wn, gr, gc, c);
    }

#pragma unroll
    for (int i = 0; i < 2; i++) {
#pragma unroll
        for (int j = 0; j < 4; j++) {
            int col = colBase + wn + j * 8 + 2 * gc;
#pragma unroll
            for (int half = 0; half < 2; half++) {
                int r = rowBase + wm + i * 16 + gr + half * 8;
                if (r >= cN) continue;
                float2 bs = *reinterpret_cast<const float2*>(g_bsum + (size_t)r * cD + col);
                float2 o = make_float2(c[i][j][half * 2] + bs.x, c[i][j][half * 2 + 1] + bs.y);
                *reinterpret_cast<float2*>(g_a + (size_t)r * cD + col) = o;
            }
        }
    }
}

// ---------------- GRU elementwise ----------------
__global__ void k_gru(const float* __restrict__ h, float* __restrict__ hout) {
    int idx = blockIdx.x * blockDim.x + threadIdx.x;
    if (idx >= cN * cD) return;
    int n = idx >> 7, d = idx & 127;
    size_t b3 = (size_t)n * cTD + d;
    float ir = g_gi[b3], iz = g_gi[b3 + 128], inn = g_gi[b3 + 256];
    float hr = g_gh[b3], hz = g_gh[b3 + 128], hn = g_gh[b3 + 256];
    float r = sigmf(ir + hr);
    float z = sigmf(iz + hz);
    float nn = tanhf(inn + r * hn);
    hout[idx] = (1.0f - z) * nn + z * h[idx];
}

// ---------------- final combine: out = sigmoid(gate_pre) * jlin ----------------
__global__ void k_combine(float* __restrict__ out) {
    int idx = blockIdx.x * blockDim.x + threadIdx.x;
    if (idx >= cN * cG) return;
    out[idx] = sigmf(g_gate[idx]) * g_a[idx];
}

// ---------------- host ----------------
extern "C" void kernel_launch(void* const* d_in, const int* in_sizes, int n_in,
                              void* d_out, int out_size) {
    (void)in_sizes; (void)n_in; (void)out_size;
    const float* features = (const float*)d_in[0];
    const int*   src      = (const int*)d_in[1];
    const int*   dst      = (const int*)d_in[2];
    const int*   etypes   = (const int*)d_in[3];
    const float* W_et     = (const float*)d_in[4];
    const float* b_et     = (const float*)d_in[5];
    const float* W_ih     = (const float*)d_in[6];
    const float* b_ih     = (const float*)d_in[7];
    const float* W_hh     = (const float*)d_in[8];
    const float* b_hh     = (const float*)d_in[9];
    const float* i_w      = (const float*)d_in[10];
    const float* i_b      = (const float*)d_in[11];
    const float* j_w      = (const float*)d_in[12];
    const float* j_b      = (const float*)d_in[13];
    float* out = (float*)d_out;

    float *h0, *h1, *abuf, *gi, *gh, *gate;
    cudaGetSymbolAddress((void**)&h0, g_h0);
    cudaGetSymbolAddress((void**)&h1, g_h1);
    cudaGetSymbolAddress((void**)&abuf, g_a);
    cudaGetSymbolAddress((void**)&gi, g_gi);
    cudaGetSymbolAddress((void**)&gh, g_gh);
    cudaGetSymbolAddress((void**)&gate, g_gate);

    cudaFuncSetAttribute(sgemm_tf32, cudaFuncAttributeMaxDynamicSharedMemorySize, SMEM_BYTES);
    cudaFuncSetAttribute(sgemm_etype_tf32, cudaFuncAttributeMaxDynamicSharedMemorySize, SMEM_BYTES);

    // ---- CSR build (sorted by dst*4+etype) ----
    k_fill_deg<<<(cM + 255) / 256, 256>>>();
    k_hist<<<(cE + 255) / 256, 256>>>(dst, etypes);
    k_scan1<<<SCAN_NB, 1024>>>();
    k_scan2<<<1, 512>>>();
    k_scan3<<<SCAN_NB, 1024>>>();
    k_copy_cur<<<(cM + 255) / 256, 256>>>();
    k_scatter<<<(cE + 255) / 256, 256>>>(src, dst, etypes);
    k_bsum<<<(cN * cD + 255) / 256, 256>>>(b_et);

    const int RB = (cN + BM - 1) / BM;  // 782 row tiles
    dim3 gA(RB, cD / BN);               // 128 output cols
    dim3 gG(RB, cTD / BN);              // 384 output cols

    const float* hc = features;
    float* houts[3] = {h0, h1, h0};
    for (int s = 0; s < 3; s++) {
        k_agg<<<(cN + 7) / 8, 256>>>(hc);
        sgemm_etype_tf32<<<gA, 256, SMEM_BYTES>>>(W_et);                              // -> g_a
        sgemm_tf32<<<gG, 256, SMEM_BYTES>>>(abuf, W_ih, cD, b_ih, gi, cTD, cN, 0);    // gi
        sgemm_tf32<<<gG, 256, SMEM_BYTES>>>(hc,   W_hh, cD, b_hh, gh, cTD, cN, 0);    // gh
        k_gru<<<(cN * cD + 255) / 256, 256>>>(hc, houts[s]);
        hc = houts[s];
    }

    // gated output head
    sgemm_tf32<<<gA, 256, SMEM_BYTES>>>(hc, i_w, 2 * cD, nullptr, gate, cG, cN, 0);
    sgemm_tf32<<<gA, 256, SMEM_BYTES>>>(features, i_w + cD, 2 * cD, i_b, gate, cG, cN, 1);
    sgemm_tf32<<<gA, 256, SMEM_BYTES>>>(hc, j_w, cD, j_b, abuf, cG, cN, 0);  // jlin -> g_a
    k_combine<<<(cN * cG + 255) / 256, 256>>>(out);
}

// round 4
// speedup vs baseline: 1.5698x; 1.1470x over previous
#include <cuda_runtime.h>
#include <cstdint>

// ---------------- problem constants ----------------
constexpr int cN = 100000;   // nodes
constexpr int cE = 1600000;  // edges
constexpr int cD = 128;      // feature dim
constexpr int cK = 4;        // etypes
constexpr int cM = cK * cN;                  // 400000 keys (dst*4+etype)
constexpr int SCAN_NB = (cM + 1023) / 1024;  // 391

// ---------------- scratch ----------------
__device__ __align__(16) float g_h0[(size_t)cN * cD];
__device__ __align__(16) float g_h1[(size_t)cN * cD];
__device__ __align__(16) float g_s[(size_t)cK * cN * cD];   // per-(etype,node) aggregated h
__device__ __align__(16) float g_a[(size_t)cN * cD];        // message result
__device__ __align__(16) float g_bsum[(size_t)cN * cD];     // sum_k cnt_k(v) * b_et[k]

__device__ int g_deg[cM];
__device__ int g_rp[cM + 1];
__device__ int g_cur[cM];
__device__ int g_esrc[cE];
__device__ int g_part[512];

// ---------------- helpers ----------------
__device__ __forceinline__ float sigmf(float x) { return 1.0f / (1.0f + __expf(-x)); }

__device__ __forceinline__ uint32_t f2tf(float x) {
    uint32_t r;
    asm("cvt.rna.tf32.f32 %0, %1;" : "=r"(r) : "f"(x));
    return r;
}

__device__ __forceinline__ void mma_tf32(float c[4], const uint32_t a[4], const uint32_t b[2]) {
    asm volatile(
        "mma.sync.aligned.m16n8k8.row.col.f32.tf32.tf32.f32 "
        "{%0,%1,%2,%3}, {%4,%5,%6,%7}, {%8,%9}, {%0,%1,%2,%3};"
        : "+f"(c[0]), "+f"(c[1]), "+f"(c[2]), "+f"(c[3])
        : "r"(a[0]), "r"(a[1]), "r"(a[2]), "r"(a[3]), "r"(b[0]), "r"(b[1]));
}

// ---------------- CSR build ----------------
__global__ void k_fill_deg() {
    int i = blockIdx.x * blockDim.x + threadIdx.x;
    if (i < cM) g_deg[i] = 0;
}
__global__ void k_hist(const int* __restrict__ dst, const int* __restrict__ et) {
    int e = blockIdx.x * blockDim.x + threadIdx.x;
    if (e < cE) atomicAdd(&g_deg[dst[e] * 4 + et[e]], 1);
}
__global__ void k_scan1() {
    __shared__ int sm[1024];
    int i = blockIdx.x * 1024 + threadIdx.x;
    int v = (i < cM) ? g_deg[i] : 0;
    sm[threadIdx.x] = v;
    __syncthreads();
    for (int off = 1; off < 1024; off <<= 1) {
        int t = 0;
        if (threadIdx.x >= off) t = sm[threadIdx.x - off];
        __syncthreads();
        sm[threadIdx.x] += t;
        __syncthreads();
    }
    if (i < cM) g_rp[i] = sm[threadIdx.x] - v;
    if (threadIdx.x == 1023) g_part[blockIdx.x] = sm[1023];
}
__global__ void k_scan2() {
    __shared__ int sm[512];
    int t = threadIdx.x;
    int v = (t < SCAN_NB) ? g_part[t] : 0;
    sm[t] = v;
    __syncthreads();
    for (int off = 1; off < 512; off <<= 1) {
        int x = 0;
        if (t >= off) x = sm[t - off];
        __syncthreads();
        sm[t] += x;
        __syncthreads();
    }
    if (t < SCAN_NB) g_part[t] = sm[t] - v;
    if (t == 511) g_rp[cM] = sm[511];
}
__global__ void k_scan3() {
    int i = blockIdx.x * 1024 + threadIdx.x;
    if (i < cM) g_rp[i] += g_part[blockIdx.x];
}
__global__ void k_copy_cur() {
    int i = blockIdx.x * blockDim.x + threadIdx.x;
    if (i < cM) g_cur[i] = g_rp[i];
}
__global__ void k_scatter(const int* __restrict__ src, const int* __restrict__ dst,
                          const int* __restrict__ et) {
    int e = blockIdx.x * blockDim.x + threadIdx.x;
    if (e < cE) {
        int key = dst[e] * 4 + et[e];
        int pos = atomicAdd(&g_cur[key], 1);
        g_esrc[pos] = src[e];
    }
}
__global__ void k_bsum(const float* __restrict__ bet) {
    int idx = blockIdx.x * blockDim.x + threadIdx.x;
    if (idx >= cN * cD) return;
    int r = idx >> 7, col = idx & 127;
    int rp[5];
#pragma unroll
    for (int k = 0; k <= 4; k++) rp[k] = g_rp[4 * r + k];
    float v = 0.f;
#pragma unroll
    for (int k = 0; k < 4; k++) v += (float)(rp[k + 1] - rp[k]) * __ldg(&bet[k * cD + col]);
    g_bsum[idx] = v;
}

// ---------------- per-step aggregation: s[k][v] = sum_{etype-k edges into v} h[src] ----------------
__global__ void k_agg(const float* __restrict__ h) {
    int warp = (blockIdx.x * blockDim.x + threadIdx.x) >> 5;
    int lane = threadIdx.x & 31;
    if (warp >= cN) return;
    const float4* hp = reinterpret_cast<const float4*>(h);
    float4* sp = reinterpret_cast<float4*>(g_s);
    int base = warp * 4;
    int r0 = g_rp[base];
#pragma unroll
    for (int k = 0; k < cK; k++) {
        int r1 = g_rp[base + k + 1];
        float4 acc = make_float4(0.f, 0.f, 0.f, 0.f);
        for (int i = r0; i < r1; i++) {
            int s = __ldg(&g_esrc[i]);
            float4 x = hp[(size_t)s * 32 + lane];
            acc.x += x.x; acc.y += x.y; acc.z += x.z; acc.w += x.w;
        }
        sp[((size_t)k * cN + warp) * 32 + lane] = acc;
        r0 = r1;
    }
}

// ---------------- shared GEMM building blocks ----------------
constexpr int LDT = 132;

__device__ __forceinline__ void load_tile_X(const float* __restrict__ X, float* Xs,
                                            int rowBase, int nrows, int tid) {
    for (int idx = tid; idx < 128 * 32; idx += 256) {
        int row = idx >> 5, c4 = idx & 31;
        float4 v = make_float4(0.f, 0.f, 0.f, 0.f);
        int r = rowBase + row;
        if (r < nrows) v = *reinterpret_cast<const float4*>(X + (size_t)r * cD + c4 * 4);
        uint32_t* d = reinterpret_cast<uint32_t*>(Xs + row * LDT + c4 * 4);
        d[0] = f2tf(v.x); d[1] = f2tf(v.y); d[2] = f2tf(v.z); d[3] = f2tf(v.w);
    }
}
// rows64: loads 64 W rows (output cols colBase..colBase+63), k=0..127
__device__ __forceinline__ void load_tile_W64(const float* __restrict__ W, int ldw, float* Ws,
                                              int colBase, int tid) {
    for (int idx = tid; idx < 64 * 32; idx += 256) {
        int o = idx >> 5, c4 = idx & 31;
        float4 v = *reinterpret_cast<const float4*>(W + (size_t)(colBase + o) * ldw + c4 * 4);
        uint32_t* d = reinterpret_cast<uint32_t*>(Ws + o * LDT + c4 * 4);
        d[0] = f2tf(v.x); d[1] = f2tf(v.y); d[2] = f2tf(v.z); d[3] = f2tf(v.w);
    }
}
__device__ __forceinline__ void load_tile_W128(const float* __restrict__ W, int ldw, float* Ws,
                                               int tid) {
    for (int idx = tid; idx < 128 * 32; idx += 256) {
        int o = idx >> 5, c4 = idx & 31;
        float4 v = *reinterpret_cast<const float4*>(W + (size_t)o * ldw + c4 * 4);
        uint32_t* d = reinterpret_cast<uint32_t*>(Ws + o * LDT + c4 * 4);
        d[0] = f2tf(v.x); d[1] = f2tf(v.y); d[2] = f2tf(v.z); d[3] = f2tf(v.w);
    }
}

// warp-tile 32x32 mainloop (BN=64 kernels)
__device__ __forceinline__ void mma_loop32(const float* Xs, const float* Ws,
                                           int wm, int wn, int gr, int gc, float c[2][4][4]) {
#pragma unroll
    for (int k0 = 0; k0 < cD; k0 += 8) {
        uint32_t a[2][4], b[4][2];
#pragma unroll
        for (int i = 0; i < 2; i++) {
            const float* base = Xs + (wm + i * 16 + gr) * LDT + k0 + gc;
            a[i][0] = __float_as_uint(base[0]);
            a[i][1] = __float_as_uint(base[8 * LDT]);
            a[i][2] = __float_as_uint(base[4]);
            a[i][3] = __float_as_uint(base[8 * LDT + 4]);
        }
#pragma unroll
        for (int j = 0; j < 4; j++) {
            const float* base = Ws + (wn + j * 8 + gr) * LDT + k0 + gc;
            b[j][0] = __float_as_uint(base[0]);
            b[j][1] = __float_as_uint(base[4]);
        }
#pragma unroll
        for (int i = 0; i < 2; i++)
#pragma unroll
            for (int j = 0; j < 4; j++) mma_tf32(c[i][j], a[i], b[j]);
    }
}
// warp-tile 32x64 mainloop (BN=128 kernels)
__device__ __forceinline__ void mma_loop64(const float* Xs, const float* Ws,
                                           int wm, int wn, int gr, int gc, float c[2][8][4]) {
#pragma unroll
    for (int k0 = 0; k0 < cD; k0 += 8) {
        uint32_t a[2][4], b[8][2];
#pragma unroll
        for (int i = 0; i < 2; i++) {
            const float* base = Xs + (wm + i * 16 + gr) * LDT + k0 + gc;
            a[i][0] = __float_as_uint(base[0]);
            a[i][1] = __float_as_uint(base[8 * LDT]);
            a[i][2] = __float_as_uint(base[4]);
            a[i][3] = __float_as_uint(base[8 * LDT + 4]);
        }
#pragma unroll
        for (int j = 0; j < 8; j++) {
            const float* base = Ws + (wn + j * 8 + gr) * LDT + k0 + gc;
            b[j][0] = __float_as_uint(base[0]);
            b[j][1] = __float_as_uint(base[4]);
        }
#pragma unroll
        for (int i = 0; i < 2; i++)
#pragma unroll
            for (int j = 0; j < 8; j++) mma_tf32(c[i][j], a[i], b[j]);
    }
}

// ---------------- etype GEMM (BN=128): a[v] = sum_k s_k[v] @ W_k^T + bsum[v] ----------------
constexpr int SM_ET = 2 * 128 * LDT * 4;  // 135168

__global__ __launch_bounds__(256, 1) void sgemm_etype_tf32(const float* __restrict__ Wet) {
    extern __shared__ float smn[];
    float* Xs = smn;
    float* Ws = smn + 128 * LDT;
    int tid = threadIdx.x;
    int rowBase = blockIdx.x * 128;
    int lane = tid & 31, warp = tid >> 5;
    int wm = (warp & 3) * 32, wn = (warp >> 2) * 64;
    int gr = lane >> 2, gc = lane & 3;

    float c[2][8][4];
#pragma unroll
    for (int i = 0; i < 2; i++)
#pragma unroll
        for (int j = 0; j < 8; j++)
#pragma unroll
            for (int q = 0; q < 4; q++) c[i][j][q] = 0.f;

    for (int ke = 0; ke < cK; ke++) {
        if (ke) __syncthreads();
        load_tile_X(g_s + (size_t)ke * cN * cD, Xs, rowBase, cN, tid);
        load_tile_W128(Wet + (size_t)ke * cD * cD, cD, Ws, tid);
        __syncthreads();
        mma_loop64(Xs, Ws, wm, wn, gr, gc, c);
    }

#pragma unroll
    for (int i = 0; i < 2; i++)
#pragma unroll
        for (int j = 0; j < 8; j++) {
            int col = wn + j * 8 + 2 * gc;
#pragma unroll
            for (int half = 0; half < 2; half++) {
                int r = rowBase + wm + i * 16 + gr + half * 8;
                if (r >= cN) continue;
                float2 bs = *reinterpret_cast<const float2*>(g_bsum + (size_t)r * cD + col);
                float2 o = make_float2(c[i][j][half * 2] + bs.x, c[i][j][half * 2 + 1] + bs.y);
                *reinterpret_cast<float2*>(g_a + (size_t)r * cD + col) = o;
            }
        }
}

// ---------------- fused GRU: h_out = GRUCell(a, h) in one kernel ----------------
// grid (782, 2); block computes 128 rows x 64 cols of h_out, looping 3 gates x (W_ih, W_hh)
constexpr int SM_GRU = (2 * 128 + 64) * LDT * 4;  // 168960

__global__ __launch_bounds__(256, 1) void k_gru_fused(
    const float* __restrict__ A, const float* __restrict__ H,
    const float* __restrict__ W_ih, const float* __restrict__ b_ih,
    const float* __restrict__ W_hh, const float* __restrict__ b_hh,
    float* __restrict__ hout) {
    extern __shared__ float smn[];
    float* Xa = smn;
    float* Xh = smn + 128 * LDT;
    float* Ws = smn + 256 * LDT;
    int tid = threadIdx.x;
    int rowBase = blockIdx.x * 128, colBase = blockIdx.y * 64;
    int lane = tid & 31, warp = tid >> 5;
    int wm = (warp & 3) * 32, wn = (warp >> 2) * 32;
    int gr = lane >> 2, gc = lane & 3;

    load_tile_X(A, Xa, rowBase, cN, tid);
    load_tile_X(H, Xh, rowBase, cN, tid);

    float rf[2][4][4], zf[2][4][4], ci[2][4][4], ch[2][4][4];

#pragma unroll
    for (int g = 0; g < 3; g++) {
#pragma unroll
        for (int i = 0; i < 2; i++)
#pragma unroll
            for (int j = 0; j < 4; j++)
#pragma unroll
                for (int q = 0; q < 4; q++) { ci[i][j][q] = 0.f; ch[i][j][q] = 0.f; }

        load_tile_W64(W_ih + (size_t)g * 128 * cD, cD, Ws, colBase, tid);
        __syncthreads();
        mma_loop32(Xa, Ws, wm, wn, gr, gc, ci);
        __syncthreads();
        load_tile_W64(W_hh + (size_t)g * 128 * cD, cD, Ws, colBase, tid);
        __syncthreads();
        mma_loop32(Xh, Ws, wm, wn, gr, gc, ch);
        __syncthreads();

#pragma unroll
        for (int i = 0; i < 2; i++)
#pragma unroll
            for (int j = 0; j < 4; j++) {
                int col = colBase + wn + j * 8 + 2 * gc;
                float bi0 = __ldg(&b_ih[g * 128 + col]), bi1 = __ldg(&b_ih[g * 128 + col + 1]);
                float bh0 = __ldg(&b_hh[g * 128 + col]), bh1 = __ldg(&b_hh[g * 128 + col + 1]);
                if (g == 0) {
#pragma unroll
                    for (int q = 0; q < 4; q++) {
                        float bi = (q & 1) ? bi1 : bi0, bh = (q & 1) ? bh1 : bh0;
                        rf[i][j][q] = sigmf(ci[i][j][q] + bi + ch[i][j][q] + bh);
                    }
                } else if (g == 1) {
#pragma unroll
                    for (int q = 0; q < 4; q++) {
                        float bi = (q & 1) ? bi1 : bi0, bh = (q & 1) ? bh1 : bh0;
                        zf[i][j][q] = sigmf(ci[i][j][q] + bi + ch[i][j][q] + bh);
                    }
                } else {
#pragma unroll
                    for (int half = 0; half < 2; half++) {
                        int r = rowBase + wm + i * 16 + gr + half * 8;
                        if (r >= cN) continue;
                        float2 hv = *reinterpret_cast<const float2*>(H + (size_t)r * cD + col);
                        int q0 = half * 2, q1 = half * 2 + 1;
                        float n0 = tanhf(ci[i][j][q0] + bi0 + rf[i][j][q0] * (ch[i][j][q0] + bh0));
                        float n1 = tanhf(ci[i][j][q1] + bi1 + rf[i][j][q1] * (ch[i][j][q1] + bh1));
                        float2 o;
                        o.x = (1.0f - zf[i][j][q0]) * n0 + zf[i][j][q0] * hv.x;
                        o.y = (1.0f - zf[i][j][q1]) * n1 + zf[i][j][q1] * hv.y;
                        *reinterpret_cast<float2*>(hout + (size_t)r * cD + col) = o;
                    }
                }
            }
    }
}

// ---------------- fused output head: out = sigmoid([h,f] @ i_w^T + i_b) * (h @ j_w^T + j_b) ----------------
constexpr int SM_HEAD = 3 * 128 * LDT * 4;  // 202752

__global__ __launch_bounds__(256, 1) void k_head(
    const float* __restrict__ H, const float* __restrict__ F,
    const float* __restrict__ i_w, const float* __restrict__ i_b,
    const float* __restrict__ j_w, const float* __restrict__ j_b,
    float* __restrict__ out) {
    extern __shared__ float smn[];
    float* Xh = smn;
    float* Xf = smn + 128 * LDT;
    float* Ws = smn + 256 * LDT;
    int tid = threadIdx.x;
    int rowBase = blockIdx.x * 128;
    int lane = tid & 31, warp = tid >> 5;
    int wm = (warp & 3) * 32, wn = (warp >> 2) * 64;
    int gr = lane >> 2, gc = lane & 3;

    load_tile_X(H, Xh, rowBase, cN, tid);
    load_tile_X(F, Xf, rowBase, cN, tid);

    float cg[2][8][4], cj[2][8][4];
#pragma unroll
    for (int i = 0; i < 2; i++)
#pragma unroll
        for (int j = 0; j < 8; j++)
#pragma unroll
            for (int q = 0; q < 4; q++) { cg[i][j][q] = 0.f; cj[i][j][q] = 0.f; }

    load_tile_W128(i_w, 2 * cD, Ws, tid);       // i_w[:, 0:128]
    __syncthreads();
    mma_loop64(Xh, Ws, wm, wn, gr, gc, cg);
    __syncthreads();
    load_tile_W128(i_w + cD, 2 * cD, Ws, tid);  // i_w[:, 128:256]
    __syncthreads();
    mma_loop64(Xf, Ws, wm, wn, gr, gc, cg);
    __syncthreads();
    load_tile_W128(j_w, cD, Ws, tid);
    __syncthreads();
    mma_loop64(Xh, Ws, wm, wn, gr, gc, cj);

#pragma unroll
    for (int i = 0; i < 2; i++)
#pragma unroll
        for (int j = 0; j < 8; j++) {
            int col = wn + j * 8 + 2 * gc;
            float ib0 = __ldg(&i_b[col]), ib1 = __ldg(&i_b[col + 1]);
            float jb0 = __ldg(&j_b[col]), jb1 = __ldg(&j_b[col + 1]);
#pragma unroll
            for (int half = 0; half < 2; half++) {
                int r = rowBase + wm + i * 16 + gr + half * 8;
                if (r >= cN) continue;
                int q0 = half * 2, q1 = half * 2 + 1;
                float2 o;
                o.x = sigmf(cg[i][j][q0] + ib0) * (cj[i][j][q0] + jb0);
                o.y = sigmf(cg[i][j][q1] + ib1) * (cj[i][j][q1] + jb1);
                *reinterpret_cast<float2*>(out + (size_t)r * cD + col) = o;
            }
        }
}

// ---------------- host ----------------
extern "C" void kernel_launch(void* const* d_in, const int* in_sizes, int n_in,
                              void* d_out, int out_size) {
    (void)in_sizes; (void)n_in; (void)out_size;
    const float* features = (const float*)d_in[0];
    const int*   src      = (const int*)d_in[1];
    const int*   dst      = (const int*)d_in[2];
    const int*   etypes   = (const int*)d_in[3];
    const float* W_et     = (const float*)d_in[4];
    const float* b_et     = (const float*)d_in[5];
    const float* W_ih     = (const float*)d_in[6];
    const float* b_ih     = (const float*)d_in[7];
    const float* W_hh     = (const float*)d_in[8];
    const float* b_hh     = (const float*)d_in[9];
    const float* i_w      = (const float*)d_in[10];
    const float* i_b      = (const float*)d_in[11];
    const float* j_w      = (const float*)d_in[12];
    const float* j_b      = (const float*)d_in[13];
    float* out = (float*)d_out;

    float *h0, *h1, *abuf;
    cudaGetSymbolAddress((void**)&h0, g_h0);
    cudaGetSymbolAddress((void**)&h1, g_h1);
    cudaGetSymbolAddress((void**)&abuf, g_a);

    cudaFuncSetAttribute(sgemm_etype_tf32, cudaFuncAttributeMaxDynamicSharedMemorySize, SM_ET);
    cudaFuncSetAttribute(k_gru_fused, cudaFuncAttributeMaxDynamicSharedMemorySize, SM_GRU);
    cudaFuncSetAttribute(k_head, cudaFuncAttributeMaxDynamicSharedMemorySize, SM_HEAD);

    // ---- CSR build (sorted by dst*4+etype) ----
    k_fill_deg<<<(cM + 255) / 256, 256>>>();
    k_hist<<<(cE + 255) / 256, 256>>>(dst, etypes);
    k_scan1<<<SCAN_NB, 1024>>>();
    k_scan2<<<1, 512>>>();
    k_scan3<<<SCAN_NB, 1024>>>();
    k_copy_cur<<<(cM + 255) / 256, 256>>>();
    k_scatter<<<(cE + 255) / 256, 256>>>(src, dst, etypes);
    k_bsum<<<(cN * cD + 255) / 256, 256>>>(b_et);

    const int RB = (cN + 127) / 128;  // 782 row tiles

    const float* hc = features;
    float* houts[3] = {h0, h1, h0};
    for (int s = 0; s < 3; s++) {
        k_agg<<<(cN + 7) / 8, 256>>>(hc);
        sgemm_etype_tf32<<<RB, 256, SM_ET>>>(W_et);  // -> g_a
        k_gru_fused<<<dim3(RB, 2), 256, SM_GRU>>>(abuf, hc, W_ih, b_ih, W_hh, b_hh, houts[s]);
        hc = houts[s];
    }
    k_head<<<RB, 256, SM_HEAD>>>(hc, features, i_w, i_b, j_w, j_b, out);
}

// round 5
// speedup vs baseline: 1.5893x; 1.0124x over previous
#include <cuda_runtime.h>
#include <cstdint>

// ---------------- problem constants ----------------
constexpr int cN = 100000;   // nodes
constexpr int cE = 1600000;  // edges
constexpr int cD = 128;      // feature dim
constexpr int cK = 4;        // etypes
constexpr int cM = cK * cN;                  // 400000 keys (dst*4+etype)
constexpr int SCAN_NB = (cM + 1023) / 1024;  // 391

// ---------------- scratch ----------------
__device__ __align__(16) float g_h0[(size_t)cN * cD];
__device__ __align__(16) float g_h1[(size_t)cN * cD];
__device__ __align__(16) float g_a[(size_t)cN * cD];        // message result
__device__ __align__(16) float g_bsum[(size_t)cN * cD];     // sum_k cnt_k(v) * b_et[k]

__device__ int g_deg[cM];
__device__ int g_rp[cM + 1];
__device__ int g_cur[cM];
__device__ int g_esrc[cE];
__device__ int g_part[512];

// ---------------- helpers ----------------
__device__ __forceinline__ float sigmf(float x) { return 1.0f / (1.0f + __expf(-x)); }

__device__ __forceinline__ uint32_t f2tf(float x) {
    uint32_t r;
    asm("cvt.rna.tf32.f32 %0, %1;" : "=r"(r) : "f"(x));
    return r;
}

__device__ __forceinline__ void mma_tf32(float c[4], const uint32_t a[4], const uint32_t b[2]) {
    asm volatile(
        "mma.sync.aligned.m16n8k8.row.col.f32.tf32.tf32.f32 "
        "{%0,%1,%2,%3}, {%4,%5,%6,%7}, {%8,%9}, {%0,%1,%2,%3};"
        : "+f"(c[0]), "+f"(c[1]), "+f"(c[2]), "+f"(c[3])
        : "r"(a[0]), "r"(a[1]), "r"(a[2]), "r"(a[3]), "r"(b[0]), "r"(b[1]));
}

// ---------------- CSR build ----------------
__global__ void k_fill_deg() {
    int i = blockIdx.x * blockDim.x + threadIdx.x;
    if (i < cM) g_deg[i] = 0;
}
__global__ void k_hist(const int* __restrict__ dst, const int* __restrict__ et) {
    int e = blockIdx.x * blockDim.x + threadIdx.x;
    if (e < cE) atomicAdd(&g_deg[dst[e] * 4 + et[e]], 1);
}
__global__ void k_scan1() {
    __shared__ int sm[1024];
    int i = blockIdx.x * 1024 + threadIdx.x;
    int v = (i < cM) ? g_deg[i] : 0;
    sm[threadIdx.x] = v;
    __syncthreads();
    for (int off = 1; off < 1024; off <<= 1) {
        int t = 0;
        if (threadIdx.x >= off) t = sm[threadIdx.x - off];
        __syncthreads();
        sm[threadIdx.x] += t;
        __syncthreads();
    }
    if (i < cM) g_rp[i] = sm[threadIdx.x] - v;
    if (threadIdx.x == 1023) g_part[blockIdx.x] = sm[1023];
}
__global__ void k_scan2() {
    __shared__ int sm[512];
    int t = threadIdx.x;
    int v = (t < SCAN_NB) ? g_part[t] : 0;
    sm[t] = v;
    __syncthreads();
    for (int off = 1; off < 512; off <<= 1) {
        int x = 0;
        if (t >= off) x = sm[t - off];
        __syncthreads();
        sm[t] += x;
        __syncthreads();
    }
    if (t < SCAN_NB) g_part[t] = sm[t] - v;
    if (t == 511) g_rp[cM] = sm[511];
}
__global__ void k_scan3() {  // also initializes g_cur
    int i = blockIdx.x * 1024 + threadIdx.x;
    if (i < cM) {
        int v = g_rp[i] + g_part[blockIdx.x];
        g_rp[i] = v;
        g_cur[i] = v;
    }
}
__global__ void k_scatter(const int* __restrict__ src, const int* __restrict__ dst,
                          const int* __restrict__ et) {
    int e = blockIdx.x * blockDim.x + threadIdx.x;
    if (e < cE) {
        int key = dst[e] * 4 + et[e];
        int pos = atomicAdd(&g_cur[key], 1);
        g_esrc[pos] = src[e];
    }
}
__global__ void k_bsum(const float* __restrict__ bet) {
    int idx = blockIdx.x * blockDim.x + threadIdx.x;
    if (idx >= cN * cD) return;
    int r = idx >> 7, col = idx & 127;
    int rp[5];
#pragma unroll
    for (int k = 0; k <= 4; k++) rp[k] = g_rp[4 * r + k];
    float v = 0.f;
#pragma unroll
    for (int k = 0; k < 4; k++) v += (float)(rp[k + 1] - rp[k]) * __ldg(&bet[k * cD + col]);
    g_bsum[idx] = v;
}

// ---------------- shared GEMM building blocks ----------------
constexpr int LDT = 132;

__device__ __forceinline__ void load_tile_X(const float* __restrict__ X, float* Xs,
                                            int rowBase, int nrows, int tid) {
    for (int idx = tid; idx < 128 * 32; idx += 256) {
        int row = idx >> 5, c4 = idx & 31;
        float4 v = make_float4(0.f, 0.f, 0.f, 0.f);
        int r = rowBase + row;
        if (r < nrows) v = *reinterpret_cast<const float4*>(X + (size_t)r * cD + c4 * 4);
        uint4 t;
        t.x = f2tf(v.x); t.y = f2tf(v.y); t.z = f2tf(v.z); t.w = f2tf(v.w);
        *reinterpret_cast<uint4*>(Xs + row * LDT + c4 * 4) = t;
    }
}
__device__ __forceinline__ void load_tile_W64(const float* __restrict__ W, int ldw, float* Ws,
                                              int colBase, int tid) {
    for (int idx = tid; idx < 64 * 32; idx += 256) {
        int o = idx >> 5, c4 = idx & 31;
        float4 v = *reinterpret_cast<const float4*>(W + (size_t)(colBase + o) * ldw + c4 * 4);
        uint4 t;
        t.x = f2tf(v.x); t.y = f2tf(v.y); t.z = f2tf(v.z); t.w = f2tf(v.w);
        *reinterpret_cast<uint4*>(Ws + o * LDT + c4 * 4) = t;
    }
}
__device__ __forceinline__ void load_tile_W128(const float* __restrict__ W, int ldw, float* Ws,
                                               int tid) {
    for (int idx = tid; idx < 128 * 32; idx += 256) {
        int o = idx >> 5, c4 = idx & 31;
        float4 v = *reinterpret_cast<const float4*>(W + (size_t)o * ldw + c4 * 4);
        uint4 t;
        t.x = f2tf(v.x); t.y = f2tf(v.y); t.z = f2tf(v.z); t.w = f2tf(v.w);
        *reinterpret_cast<uint4*>(Ws + o * LDT + c4 * 4) = t;
    }
}

// warp-tile 32x32 mainloop
__device__ __forceinline__ void mma_loop32(const float* Xs, const float* Ws,
                                           int wm, int wn, int gr, int gc, float c[2][4][4]) {
#pragma unroll
    for (int k0 = 0; k0 < cD; k0 += 8) {
        uint32_t a[2][4], b[4][2];
#pragma unroll
        for (int i = 0; i < 2; i++) {
            const float* base = Xs + (wm + i * 16 + gr) * LDT + k0 + gc;
            a[i][0] = __float_as_uint(base[0]);
            a[i][1] = __float_as_uint(base[8 * LDT]);
            a[i][2] = __float_as_uint(base[4]);
            a[i][3] = __float_as_uint(base[8 * LDT + 4]);
        }
#pragma unroll
        for (int j = 0; j < 4; j++) {
            const float* base = Ws + (wn + j * 8 + gr) * LDT + k0 + gc;
            b[j][0] = __float_as_uint(base[0]);
            b[j][1] = __float_as_uint(base[4]);
        }
#pragma unroll
        for (int i = 0; i < 2; i++)
#pragma unroll
            for (int j = 0; j < 4; j++) mma_tf32(c[i][j], a[i], b[j]);
    }
}
// warp-tile 32x64 mainloop
__device__ __forceinline__ void mma_loop64(const float* Xs, const float* Ws,
                                           int wm, int wn, int gr, int gc, float c[2][8][4]) {
#pragma unroll
    for (int k0 = 0; k0 < cD; k0 += 8) {
        uint32_t a[2][4], b[8][2];
#pragma unroll
        for (int i = 0; i < 2; i++) {
            const float* base = Xs + (wm + i * 16 + gr) * LDT + k0 + gc;
            a[i][0] = __float_as_uint(base[0]);
            a[i][1] = __float_as_uint(base[8 * LDT]);
            a[i][2] = __float_as_uint(base[4]);
            a[i][3] = __float_as_uint(base[8 * LDT + 4]);
        }
#pragma unroll
        for (int j = 0; j < 8; j++) {
            const float* base = Ws + (wn + j * 8 + gr) * LDT + k0 + gc;
            b[j][0] = __float_as_uint(base[0]);
            b[j][1] = __float_as_uint(base[4]);
        }
#pragma unroll
        for (int i = 0; i < 2; i++)
#pragma unroll
            for (int j = 0; j < 8; j++) mma_tf32(c[i][j], a[i], b[j]);
    }
}

// ---------------- fused aggregation + etype GEMM ----------------
// Block: 64 nodes x all 128 output cols. For each etype: aggregate neighbor h-rows
// straight into the smem A-tile (fp32 regs -> tf32 smem), then MMA with W_k.
// a[v] = sum_k (sum_{etype-k edges into v} h[src]) @ W_k^T + bsum[v]
constexpr int SM_AE = (64 + 128) * LDT * 4;  // 101376 -> 2 CTAs/SM

__global__ __launch_bounds__(256, 2) void k_agg_etype(const float* __restrict__ h,
                                                      const float* __restrict__ Wet) {
    extern __shared__ float smn[];
    float* Xs = smn;             // 64 x LDT (tf32 aggregated tile)
    float* Ws = smn + 64 * LDT;  // 128 x LDT
    int tid = threadIdx.x, lane = tid & 31, warp = tid >> 5;
    int rowBase = blockIdx.x * 64;
    int wm = (warp & 1) * 32, wn = (warp >> 1) * 32;
    int gr = lane >> 2, gc = lane & 3;
    const float4* hp = reinterpret_cast<const float4*>(h);

    float c[2][4][4];
#pragma unroll
    for (int i = 0; i < 2; i++)
#pragma unroll
        for (int j = 0; j < 4; j++)
#pragma unroll
            for (int q = 0; q < 4; q++) c[i][j][q] = 0.f;

    for (int ke = 0; ke < cK; ke++) {
        if (ke) __syncthreads();  // all warps done reading Xs/Ws of previous etype
        // ---- aggregate: 8 nodes per warp, lane covers 4 feature cols ----
#pragma unroll
        for (int i = 0; i < 8; i++) {
            int vl = warp * 8 + i;
            int v = rowBase + vl;
            float4 acc = make_float4(0.f, 0.f, 0.f, 0.f);
            if (v < cN) {
                int r0 = __ldg(&g_rp[4 * v + ke]), r1 = __ldg(&g_rp[4 * v + ke + 1]);
                int e = r0;
                for (; e + 4 <= r1; e += 4) {  // MLP-4 gather
                    int s0 = __ldg(&g_esrc[e]), s1 = __ldg(&g_esrc[e + 1]);
                    int s2 = __ldg(&g_esrc[e + 2]), s3 = __ldg(&g_esrc[e + 3]);
                    float4 x0 = hp[(size_t)s0 * 32 + lane];
                    float4 x1 = hp[(size_t)s1 * 32 + lane];
                    float4 x2 = hp[(size_t)s2 * 32 + lane];
                    float4 x3 = hp[(size_t)s3 * 32 + lane];
                    acc.x += (x0.x + x1.x) + (x2.x + x3.x);
                    acc.y += (x0.y + x1.y) + (x2.y + x3.y);
                    acc.z += (x0.z + x1.z) + (x2.z + x3.z);
                    acc.w += (x0.w + x1.w) + (x2.w + x3.w);
                }
                for (; e < r1; e++) {
                    int s = __ldg(&g_esrc[e]);
                    float4 x = hp[(size_t)s * 32 + lane];
                    acc.x += x.x; acc.y += x.y; acc.z += x.z; acc.w += x.w;
                }
            }
            uint4 t;
            t.x = f2tf(acc.x); t.y = f2tf(acc.y); t.z = f2tf(acc.z); t.w = f2tf(acc.w);
            *reinterpret_cast<uint4*>(Xs + vl * LDT + lane * 4) = t;
        }
        load_tile_W128(Wet + (size_t)ke * cD * cD, cD, Ws, tid);
        __syncthreads();
        mma_loop32(Xs, Ws, wm, wn, gr, gc, c);
    }

#pragma unroll
    for (int i = 0; i < 2; i++)
#pragma unroll
        for (int j = 0; j < 4; j++) {
            int col = wn + j * 8 + 2 * gc;
#pragma unroll
            for (int half = 0; half < 2; half++) {
                int r = rowBase + wm + i * 16 + gr + half * 8;
                if (r >= cN) continue;
                float2 bs = *reinterpret_cast<const float2*>(g_bsum + (size_t)r * cD + col);
                float2 o = make_float2(c[i][j][half * 2] + bs.x, c[i][j][half * 2 + 1] + bs.y);
                *reinterpret_cast<float2*>(g_a + (size_t)r * cD + col) = o;
            }
        }
}

// ---------------- fused GRU: h_out = GRUCell(a, h) ----------------
constexpr int SM_GRU = (2 * 128 + 64) * LDT * 4;  // 168960

__global__ __launch_bounds__(256, 1) void k_gru_fused(
    const float* __restrict__ A, const float* __restrict__ H,
    const float* __restrict__ W_ih, const float* __restrict__ b_ih,
    const float* __restrict__ W_hh, const float* __restrict__ b_hh,
    float* __restrict__ hout) {
    extern __shared__ float smn[];
    float* Xa = smn;
    float* Xh = smn + 128 * LDT;
    float* Ws = smn + 256 * LDT;
    int tid = threadIdx.x;
    int rowBase = blockIdx.x * 128, colBase = blockIdx.y * 64;
    int lane = tid & 31, warp = tid >> 5;
    int wm = (warp & 3) * 32, wn = (warp >> 2) * 32;
    int gr = lane >> 2, gc = lane & 3;

    load_tile_X(A, Xa, rowBase, cN, tid);
    load_tile_X(H, Xh, rowBase, cN, tid);

    float rf[2][4][4], zf[2][4][4], ci[2][4][4], ch[2][4][4];

#pragma unroll
    for (int g = 0; g < 3; g++) {
#pragma unroll
        for (int i = 0; i < 2; i++)
#pragma unroll
            for (int j = 0; j < 4; j++)
#pragma unroll
                for (int q = 0; q < 4; q++) { ci[i][j][q] = 0.f; ch[i][j][q] = 0.f; }

        load_tile_W64(W_ih + (size_t)g * 128 * cD, cD, Ws, colBase, tid);
        __syncthreads();
        mma_loop32(Xa, Ws, wm, wn, gr, gc, ci);
        __syncthreads();
        load_tile_W64(W_hh + (size_t)g * 128 * cD, cD, Ws, colBase, tid);
        __syncthreads();
        mma_loop32(Xh, Ws, wm, wn, gr, gc, ch);
        __syncthreads();

#pragma unroll
        for (int i = 0; i < 2; i++)
#pragma unroll
            for (int j = 0; j < 4; j++) {
                int col = colBase + wn + j * 8 + 2 * gc;
                float bi0 = __ldg(&b_ih[g * 128 + col]), bi1 = __ldg(&b_ih[g * 128 + col + 1]);
                float bh0 = __ldg(&b_hh[g * 128 + col]), bh1 = __ldg(&b_hh[g * 128 + col + 1]);
                if (g == 0) {
#pragma unroll
                    for (int q = 0; q < 4; q++) {
                        float bi = (q & 1) ? bi1 : bi0, bh = (q & 1) ? bh1 : bh0;
                        rf[i][j][q] = sigmf(ci[i][j][q] + bi + ch[i][j][q] + bh);
                    }
                } else if (g == 1) {
#pragma unroll
                    for (int q = 0; q < 4; q++) {
                        float bi = (q & 1) ? bi1 : bi0, bh = (q & 1) ? bh1 : bh0;
                        zf[i][j][q] = sigmf(ci[i][j][q] + bi + ch[i][j][q] + bh);
                    }
                } else {
#pragma unroll
                    for (int half = 0; half < 2; half++) {
                        int r = rowBase + wm + i * 16 + gr + half * 8;
                        if (r >= cN) continue;
                        float2 hv = *reinterpret_cast<const float2*>(H + (size_t)r * cD + col);
                        int q0 = half * 2, q1 = half * 2 + 1;
                        float n0 = tanhf(ci[i][j][q0] + bi0 + rf[i][j][q0] * (ch[i][j][q0] + bh0));
                        float n1 = tanhf(ci[i][j][q1] + bi1 + rf[i][j][q1] * (ch[i][j][q1] + bh1));
                        float2 o;
                        o.x = (1.0f - zf[i][j][q0]) * n0 + zf[i][j][q0] * hv.x;
                        o.y = (1.0f - zf[i][j][q1]) * n1 + zf[i][j][q1] * hv.y;
                        *reinterpret_cast<float2*>(hout + (size_t)r * cD + col) = o;
                    }
                }
            }
    }
}

// ---------------- fused output head ----------------
constexpr int SM_HEAD = 3 * 128 * LDT * 4;  // 202752

__global__ __launch_bounds__(256, 1) void k_head(
    const float* __restrict__ H, const float* __restrict__ F,
    const float* __restrict__ i_w, const float* __restrict__ i_b,
    const float* __restrict__ j_w, const float* __restrict__ j_b,
    float* __restrict__ out) {
    extern __shared__ float smn[];
    float* Xh = smn;
    float* Xf = smn + 128 * LDT;
    float* Ws = smn + 256 * LDT;
    int tid = threadIdx.x;
    int rowBase = blockIdx.x * 128;
    int lane = tid & 31, warp = tid >> 5;
    int wm = (warp & 3) * 32, wn = (warp >> 2) * 64;
    int gr = lane >> 2, gc = lane & 3;

    load_tile_X(H, Xh, rowBase, cN, tid);
    load_tile_X(F, Xf, rowBase, cN, tid);

    float cg[2][8][4], cj[2][8][4];
#pragma unroll
    for (int i = 0; i < 2; i++)
#pragma unroll
        for (int j = 0; j < 8; j++)
#pragma unroll
            for (int q = 0; q < 4; q++) { cg[i][j][q] = 0.f; cj[i][j][q] = 0.f; }

    load_tile_W128(i_w, 2 * cD, Ws, tid);
    __syncthreads();
    mma_loop64(Xh, Ws, wm, wn, gr, gc, cg);
    __syncthreads();
    load_tile_W128(i_w + cD, 2 * cD, Ws, tid);
    __syncthreads();
    mma_loop64(Xf, Ws, wm, wn, gr, gc, cg);
    __syncthreads();
    load_tile_W128(j_w, cD, Ws, tid);
    __syncthreads();
    mma_loop64(Xh, Ws, wm, wn, gr, gc, cj);

#pragma unroll
    for (int i = 0; i < 2; i++)
#pragma unroll
        for (int j = 0; j < 8; j++) {
            int col = wn + j * 8 + 2 * gc;
            float ib0 = __ldg(&i_b[col]), ib1 = __ldg(&i_b[col + 1]);
            float jb0 = __ldg(&j_b[col]), jb1 = __ldg(&j_b[col + 1]);
#pragma unroll
            for (int half = 0; half < 2; half++) {
                int r = rowBase + wm + i * 16 + gr + half * 8;
                if (r >= cN) continue;
                int q0 = half * 2, q1 = half * 2 + 1;
                float2 o;
                o.x = sigmf(cg[i][j][q0] + ib0) * (cj[i][j][q0] + jb0);
                o.y = sigmf(cg[i][j][q1] + ib1) * (cj[i][j][q1] + jb1);
                *reinterpret_cast<float2*>(out + (size_t)r * cD + col) = o;
            }
        }
}

// ---------------- host ----------------
extern "C" void kernel_launch(void* const* d_in, const int* in_sizes, int n_in,
                              void* d_out, int out_size) {
    (void)in_sizes; (void)n_in; (void)out_size;
    const float* features = (const float*)d_in[0];
    const int*   src      = (const int*)d_in[1];
    const int*   dst      = (const int*)d_in[2];
    const int*   etypes   = (const int*)d_in[3];
    const float* W_et     = (const float*)d_in[4];
    const float* b_et     = (const float*)d_in[5];
    const float* W_ih     = (const float*)d_in[6];
    const float* b_ih     = (const float*)d_in[7];
    const float* W_hh     = (const float*)d_in[8];
    const float* b_hh     = (const float*)d_in[9];
    const float* i_w      = (const float*)d_in[10];
    const float* i_b      = (const float*)d_in[11];
    const float* j_w      = (const float*)d_in[12];
    const float* j_b      = (const float*)d_in[13];
    float* out = (float*)d_out;

    float *h0, *h1, *abuf;
    cudaGetSymbolAddress((void**)&h0, g_h0);
    cudaGetSymbolAddress((void**)&h1, g_h1);
    cudaGetSymbolAddress((void**)&abuf, g_a);

    cudaFuncSetAttribute(k_agg_etype, cudaFuncAttributeMaxDynamicSharedMemorySize, SM_AE);
    cudaFuncSetAttribute(k_gru_fused, cudaFuncAttributeMaxDynamicSharedMemorySize, SM_GRU);
    cudaFuncSetAttribute(k_head, cudaFuncAttributeMaxDynamicSharedMemorySize, SM_HEAD);

    // ---- CSR build (sorted by dst*4+etype) ----
    k_fill_deg<<<(cM + 255) / 256, 256>>>();
    k_hist<<<(cE + 255) / 256, 256>>>(dst, etypes);
    k_scan1<<<SCAN_NB, 1024>>>();
    k_scan2<<<1, 512>>>();
    k_scan3<<<SCAN_NB, 1024>>>();
    k_scatter<<<(cE + 255) / 256, 256>>>(src, dst, etypes);
    k_bsum<<<(cN * cD + 255) / 256, 256>>>(b_et);

    const int RB64 = (cN + 63) / 64;    // 1563
    const int RB128 = (cN + 127) / 128; // 782

    const float* hc = features;
    float* houts[3] = {h0, h1, h0};
    for (int s = 0; s < 3; s++) {
        k_agg_etype<<<RB64, 256, SM_AE>>>(hc, W_et);  // -> g_a
        k_gru_fused<<<dim3(RB128, 2), 256, SM_GRU>>>(abuf, hc, W_ih, b_ih, W_hh, b_hh, houts[s]);
        hc = houts[s];
    }
    k_head<<<RB128, 256, SM_HEAD>>>(hc, features, i_w, i_b, j_w, j_b, out);
}

// round 7
// speedup vs baseline: 2.5654x; 1.6142x over previous
#include <cuda_runtime.h>
#include <cuda_fp16.h>
#include <cstdint>

// ---------------- problem constants ----------------
constexpr int cN = 100000;   // nodes
constexpr int cE = 1600000;  // edges
constexpr int cD = 128;      // feature dim
constexpr int cK = 4;        // etypes
constexpr int cM = cK * cN;                  // 400000 keys (dst*4+etype)
constexpr int SCAN_NB = (cM + 1023) / 1024;  // 391

// ---------------- scratch ----------------
__device__ __align__(16) float g_h0[(size_t)cN * cD];
__device__ __align__(16) float g_h1[(size_t)cN * cD];
__device__ __align__(16) float g_a[(size_t)cN * cD];
__device__ __align__(16) float g_bsum[(size_t)cN * cD];

__device__ int g_deg[cM];
__device__ int g_rp[cM + 1];
__device__ int g_cur[cM];
__device__ int g_esrc[cE];
__device__ int g_part[512];

// ---------------- helpers ----------------
__device__ __forceinline__ float sigmf(float x) { return 1.0f / (1.0f + __expf(-x)); }

__device__ __forceinline__ uint32_t pk2(float x, float y) {
    __half2 h = __floats2half2_rn(x, y);
    return *reinterpret_cast<uint32_t*>(&h);
}

__device__ __forceinline__ void mma_f16(float c[4], const uint32_t a[4], const uint32_t b[2]) {
    asm volatile(
        "mma.sync.aligned.m16n8k16.row.col.f32.f16.f16.f32 "
        "{%0,%1,%2,%3}, {%4,%5,%6,%7}, {%8,%9}, {%0,%1,%2,%3};"
        : "+f"(c[0]), "+f"(c[1]), "+f"(c[2]), "+f"(c[3])
        : "r"(a[0]), "r"(a[1]), "r"(a[2]), "r"(a[3]), "r"(b[0]), "r"(b[1]));
}

// ---------------- CSR build ----------------
__global__ void k_fill_deg() {
    int i = blockIdx.x * blockDim.x + threadIdx.x;
    if (i < cM) g_deg[i] = 0;
}
__global__ void k_hist(const int* __restrict__ dst, const int* __restrict__ et) {
    int e = blockIdx.x * blockDim.x + threadIdx.x;
    if (e < cE) atomicAdd(&g_deg[dst[e] * 4 + et[e]], 1);
}
__global__ void k_scan1() {
    __shared__ int sm[1024];
    int i = blockIdx.x * 1024 + threadIdx.x;
    int v = (i < cM) ? g_deg[i] : 0;
    sm[threadIdx.x] = v;
    __syncthreads();
    for (int off = 1; off < 1024; off <<= 1) {
        int t = 0;
        if (threadIdx.x >= off) t = sm[threadIdx.x - off];
        __syncthreads();
        sm[threadIdx.x] += t;
        __syncthreads();
    }
    if (i < cM) g_rp[i] = sm[threadIdx.x] - v;
    if (threadIdx.x == 1023) g_part[blockIdx.x] = sm[1023];
}
__global__ void k_scan2() {
    __shared__ int sm[512];
    int t = threadIdx.x;
    int v = (t < SCAN_NB) ? g_part[t] : 0;
    sm[t] = v;
    __syncthreads();
    for (int off = 1; off < 512; off <<= 1) {
        int x = 0;
        if (t >= off) x = sm[t - off];
        __syncthreads();
        sm[t] += x;
        __syncthreads();
    }
    if (t < SCAN_NB) g_part[t] = sm[t] - v;
    if (t == 511) g_rp[cM] = sm[511];
}
__global__ void k_scan3() {  // also initializes g_cur
    int i = blockIdx.x * 1024 + threadIdx.x;
    if (i < cM) {
        int v = g_rp[i] + g_part[blockIdx.x];
        g_rp[i] = v;
        g_cur[i] = v;
    }
}
__global__ void k_scatter(const int* __restrict__ src, const int* __restrict__ dst,
                          const int* __restrict__ et) {
    int e = blockIdx.x * blockDim.x + threadIdx.x;
    if (e < cE) {
        int key = dst[e] * 4 + et[e];
        int pos = atomicAdd(&g_cur[key], 1);
        g_esrc[pos] = src[e];
    }
}
__global__ void k_bsum(const float* __restrict__ bet) {
    int idx = blockIdx.x * blockDim.x + threadIdx.x;
    if (idx >= cN * cD) return;
    int r = idx >> 7, col = idx & 127;
    int rp[5];
#pragma unroll
    for (int k = 0; k <= 4; k++) rp[k] = g_rp[4 * r + k];
    float v = 0.f;
#pragma unroll
    for (int k = 0; k < 4; k++) v += (float)(rp[k + 1] - rp[k]) * __ldg(&bet[k * cD + col]);
    g_bsum[idx] = v;
}

// ---------------- fp16 GEMM building blocks ----------------
constexpr int LD2 = 136;  // halves per smem row (272B stride, conflict-free)

__device__ __forceinline__ void load_tile_X16(const float* __restrict__ X, __half* Xs,
                                              int rowBase, int nrows, int tid) {
    for (int idx = tid; idx < 128 * 32; idx += 256) {
        int row = idx >> 5, c4 = (idx & 31) * 4;
        float4 v = make_float4(0.f, 0.f, 0.f, 0.f);
        int r = rowBase + row;
        if (r < nrows) v = *reinterpret_cast<const float4*>(X + (size_t)r * cD + c4);
        *reinterpret_cast<uint2*>(Xs + row * LD2 + c4) = make_uint2(pk2(v.x, v.y), pk2(v.z, v.w));
    }
}
__device__ __forceinline__ void load_tile_W64_16(const float* __restrict__ W, int ldw, __half* Ws,
                                                 int colBase, int tid) {
    for (int idx = tid; idx < 64 * 32; idx += 256) {
        int o = idx >> 5, c4 = (idx & 31) * 4;
        float4 v = *reinterpret_cast<const float4*>(W + (size_t)(colBase + o) * ldw + c4);
        *reinterpret_cast<uint2*>(Ws + o * LD2 + c4) = make_uint2(pk2(v.x, v.y), pk2(v.z, v.w));
    }
}
__device__ __forceinline__ void load_tile_W128_16(const float* __restrict__ W, int ldw, __half* Ws,
                                                  int tid) {
    for (int idx = tid; idx < 128 * 32; idx += 256) {
        int o = idx >> 5, c4 = (idx & 31) * 4;
        float4 v = *reinterpret_cast<const float4*>(W + (size_t)o * ldw + c4);
        *reinterpret_cast<uint2*>(Ws + o * LD2 + c4) = make_uint2(pk2(v.x, v.y), pk2(v.z, v.w));
    }
}
__device__ __forceinline__ uint32_t lds32(const __half* p) {
    return *reinterpret_cast<const uint32_t*>(p);
}

// warp-tile 32x32 mainloop, fp16 k16
__device__ __forceinline__ void mma_loop32(const __half* Xs, const __half* Ws,
                                           int wm, int wn, int gr, int gc, float c[2][4][4]) {
#pragma unroll
    for (int k0 = 0; k0 < cD; k0 += 16) {
        uint32_t a[2][4], b[4][2];
#pragma unroll
        for (int i = 0; i < 2; i++) {
            const __half* base = Xs + (wm + i * 16 + gr) * LD2 + k0 + 2 * gc;
            a[i][0] = lds32(base);
            a[i][1] = lds32(base + 8 * LD2);
            a[i][2] = lds32(base + 8);
            a[i][3] = lds32(base + 8 * LD2 + 8);
        }
#pragma unroll
        for (int j = 0; j < 4; j++) {
            const __half* base = Ws + (wn + j * 8 + gr) * LD2 + k0 + 2 * gc;
            b[j][0] = lds32(base);
            b[j][1] = lds32(base + 8);
        }
#pragma unroll
        for (int i = 0; i < 2; i++)
#pragma unroll
            for (int j = 0; j < 4; j++) mma_f16(c[i][j], a[i], b[j]);
    }
}
// warp-tile 32x64 mainloop, fp16 k16
__device__ __forceinline__ void mma_loop64(const __half* Xs, const __half* Ws,
                                           int wm, int wn, int gr, int gc, float c[2][8][4]) {
#pragma unroll
    for (int k0 = 0; k0 < cD; k0 += 16) {
        uint32_t a[2][4], b[8][2];
#pragma unroll
        for (int i = 0; i < 2; i++) {
            const __half* base = Xs + (wm + i * 16 + gr) * LD2 + k0 + 2 * gc;
            a[i][0] = lds32(base);
            a[i][1] = lds32(base + 8 * LD2);
            a[i][2] = lds32(base + 8);
            a[i][3] = lds32(base + 8 * LD2 + 8);
        }
#pragma unroll
        for (int j = 0; j < 8; j++) {
            const __half* base = Ws + (wn + j * 8 + gr) * LD2 + k0 + 2 * gc;
            b[j][0] = lds32(base);
            b[j][1] = lds32(base + 8);
        }
#pragma unroll
        for (int i = 0; i < 2; i++)
#pragma unroll
            for (int j = 0; j < 8; j++) mma_f16(c[i][j], a[i], b[j]);
    }
}

// ---------------- fused aggregation + etype GEMM ----------------
// Block: 64 nodes x all 128 output cols; f16 tiles; 3 CTAs/SM
constexpr int SM_AE = (64 + 128) * LD2 * 2;  // 52224

__global__ __launch_bounds__(256, 3) void k_agg_etype(const float* __restrict__ h,
                                                      const float* __restrict__ Wet) {
    extern __shared__ __half smh[];
    __half* Xs = smh;             // 64 x LD2
    __half* Ws = smh + 64 * LD2;  // 128 x LD2
    int tid = threadIdx.x, lane = tid & 31, warp = tid >> 5;
    int rowBase = blockIdx.x * 64;
    int wm = (warp & 1) * 32, wn = (warp >> 1) * 32;
    int gr = lane >> 2, gc = lane & 3;
    const float4* hp = reinterpret_cast<const float4*>(h);

    float c[2][4][4];
#pragma unroll
    for (int i = 0; i < 2; i++)
#pragma unroll
        for (int j = 0; j < 4; j++)
#pragma unroll
            for (int q = 0; q < 4; q++) c[i][j][q] = 0.f;

    for (int ke = 0; ke < cK; ke++) {
        if (ke) __syncthreads();
#pragma unroll
        for (int i = 0; i < 8; i++) {
            int vl = warp * 8 + i;
            int v = rowBase + vl;
            float4 acc = make_float4(0.f, 0.f, 0.f, 0.f);
            if (v < cN) {
                int r0 = __ldg(&g_rp[4 * v + ke]), r1 = __ldg(&g_rp[4 * v + ke + 1]);
                int e = r0;
                for (; e + 4 <= r1; e += 4) {
                    int s0 = __ldg(&g_esrc[e]), s1 = __ldg(&g_esrc[e + 1]);
                    int s2 = __ldg(&g_esrc[e + 2]), s3 = __ldg(&g_esrc[e + 3]);
                    float4 x0 = hp[(size_t)s0 * 32 + lane];
                    float4 x1 = hp[(size_t)s1 * 32 + lane];
                    float4 x2 = hp[(size_t)s2 * 32 + lane];
                    float4 x3 = hp[(size_t)s3 * 32 + lane];
                    acc.x += (x0.x + x1.x) + (x2.x + x3.x);
                    acc.y += (x0.y + x1.y) + (x2.y + x3.y);
                    acc.z += (x0.z + x1.z) + (x2.z + x3.z);
                    acc.w += (x0.w + x1.w) + (x2.w + x3.w);
                }
                for (; e < r1; e++) {
                    int s = __ldg(&g_esrc[e]);
                    float4 x = hp[(size_t)s * 32 + lane];
                    acc.x += x.x; acc.y += x.y; acc.z += x.z; acc.w += x.w;
                }
            }
            *reinterpret_cast<uint2*>(Xs + vl * LD2 + lane * 4) =
                make_uint2(pk2(acc.x, acc.y), pk2(acc.z, acc.w));
        }
        load_tile_W128_16(Wet + (size_t)ke * cD * cD, cD, Ws, tid);
        __syncthreads();
        mma_loop32(Xs, Ws, wm, wn, gr, gc, c);
    }

#pragma unroll
    for (int i = 0; i < 2; i++)
#pragma unroll
        for (int j = 0; j < 4; j++) {
            int col = wn + j * 8 + 2 * gc;
#pragma unroll
            for (int half = 0; half < 2; half++) {
                int r = rowBase + wm + i * 16 + gr + half * 8;
                if (r >= cN) continue;
                float2 bs = *reinterpret_cast<const float2*>(g_bsum + (size_t)r * cD + col);
                float2 o = make_float2(c[i][j][half * 2] + bs.x, c[i][j][half * 2 + 1] + bs.y);
                *reinterpret_cast<float2*>(g_a + (size_t)r * cD + col) = o;
            }
        }
}

// ---------------- fused GRU: h_out = GRUCell(a, h) ----------------
constexpr int SM_GRU = (2 * 128 + 64) * LD2 * 2;  // 87040 -> 2 CTAs/SM

__global__ __launch_bounds__(256, 2) void k_gru_fused(
    const float* __restrict__ A, const float* __restrict__ H,
    const float* __restrict__ W_ih, const float* __restrict__ b_ih,
    const float* __restrict__ W_hh, const float* __restrict__ b_hh,
    float* __restrict__ hout) {
    extern __shared__ __half smh[];
    __half* Xa = smh;
    __half* Xh = smh + 128 * LD2;
    __half* Ws = smh + 256 * LD2;
    int tid = threadIdx.x;
    int rowBase = blockIdx.x * 128, colBase = blockIdx.y * 64;
    int lane = tid & 31, warp = tid >> 5;
    int wm = (warp & 3) * 32, wn = (warp >> 2) * 32;
    int gr = lane >> 2, gc = lane & 3;

    load_tile_X16(A, Xa, rowBase, cN, tid);
    load_tile_X16(H, Xh, rowBase, cN, tid);

    float rf[2][4][4], zf[2][4][4], ci[2][4][4], ch[2][4][4];

#pragma unroll
    for (int g = 0; g < 3; g++) {
#pragma unroll
        for (int i = 0; i < 2; i++)
#pragma unroll
            for (int j = 0; j < 4; j++)
#pragma unroll
                for (int q = 0; q < 4; q++) { ci[i][j][q] = 0.f; ch[i][j][q] = 0.f; }

        load_tile_W64_16(W_ih + (size_t)g * 128 * cD, cD, Ws, colBase, tid);
        __syncthreads();
        mma_loop32(Xa, Ws, wm, wn, gr, gc, ci);
        __syncthreads();
        load_tile_W64_16(W_hh + (size_t)g * 128 * cD, cD, Ws, colBase, tid);
        __syncthreads();
        mma_loop32(Xh, Ws, wm, wn, gr, gc, ch);
        __syncthreads();

#pragma unroll
        for (int i = 0; i < 2; i++)
#pragma unroll
            for (int j = 0; j < 4; j++) {
                int col = colBase + wn + j * 8 + 2 * gc;
                float bi0 = __ldg(&b_ih[g * 128 + col]), bi1 = __ldg(&b_ih[g * 128 + col + 1]);
                float bh0 = __ldg(&b_hh[g * 128 + col]), bh1 = __ldg(&b_hh[g * 128 + col + 1]);
                if (g == 0) {
#pragma unroll
                    for (int q = 0; q < 4; q++) {
                        float bi = (q & 1) ? bi1 : bi0, bh = (q & 1) ? bh1 : bh0;
                        rf[i][j][q] = sigmf(ci[i][j][q] + bi + ch[i][j][q] + bh);
                    }
                } else if (g == 1) {
#pragma unroll
                    for (int q = 0; q < 4; q++) {
                        float bi = (q & 1) ? bi1 : bi0, bh = (q & 1) ? bh1 : bh0;
                        zf[i][j][q] = sigmf(ci[i][j][q] + bi + ch[i][j][q] + bh);
                    }
                } else {
#pragma unroll
                    for (int half = 0; half < 2; half++) {
                        int r = rowBase + wm + i * 16 + gr + half * 8;
                        if (r >= cN) continue;
                        float2 hv = *reinterpret_cast<const float2*>(H + (size_t)r * cD + col);
                        int q0 = half * 2, q1 = half * 2 + 1;
                        float n0 = tanhf(ci[i][j][q0] + bi0 + rf[i][j][q0] * (ch[i][j][q0] + bh0));
                        float n1 = tanhf(ci[i][j][q1] + bi1 + rf[i][j][q1] * (ch[i][j][q1] + bh1));
                        float2 o;
                        o.x = (1.0f - zf[i][j][q0]) * n0 + zf[i][j][q0] * hv.x;
                        o.y = (1.0f - zf[i][j][q1]) * n1 + zf[i][j][q1] * hv.y;
                        *reinterpret_cast<float2*>(hout + (size_t)r * cD + col) = o;
                    }
                }
            }
    }
}

// ---------------- fused output head ----------------
constexpr int SM_HEAD = 3 * 128 * LD2 * 2;  // 104448 -> 2 CTAs/SM

__global__ __launch_bounds__(256, 2) void k_head(
    const float* __restrict__ H, const float* __restrict__ F,
    const float* __restrict__ i_w, const float* __restrict__ i_b,
    const float* __restrict__ j_w, const float* __restrict__ j_b,
    float* __restrict__ out) {
    extern __shared__ __half smh[];
    __half* Xh = smh;
    __half* Xf = smh + 128 * LD2;
    __half* Ws = smh + 256 * LD2;
    int tid = threadIdx.x;
    int rowBase = blockIdx.x * 128;
    int lane = tid & 31, warp = tid >> 5;
    int wm = (warp & 3) * 32, wn = (warp >> 2) * 64;
    int gr = lane >> 2, gc = lane & 3;

    load_tile_X16(H, Xh, rowBase, cN, tid);
    load_tile_X16(F, Xf, rowBase, cN, tid);

    float cg[2][8][4], cj[2][8][4];
#pragma unroll
    for (int i = 0; i < 2; i++)
#pragma unroll
        for (int j = 0; j < 8; j++)
#pragma unroll
            for (int q = 0; q < 4; q++) { cg[i][j][q] = 0.f; cj[i][j][q] = 0.f; }

    load_tile_W128_16(i_w, 2 * cD, Ws, tid);
    __syncthreads();
    mma_loop64(Xh, Ws, wm, wn, gr, gc, cg);
    __syncthreads();
    load_tile_W128_16(i_w + cD, 2 * cD, Ws, tid);
    __syncthreads();
    mma_loop64(Xf, Ws, wm, wn, gr, gc, cg);
    __syncthreads();
    load_tile_W128_16(j_w, cD, Ws, tid);
    __syncthreads();
    mma_loop64(Xh, Ws, wm, wn, gr, gc, cj);

#pragma unroll
    for (int i = 0; i < 2; i++)
#pragma unroll
        for (int j = 0; j < 8; j++) {
            int col = wn + j * 8 + 2 * gc;
            float ib0 = __ldg(&i_b[col]), ib1 = __ldg(&i_b[col + 1]);
            float jb0 = __ldg(&j_b[col]), jb1 = __ldg(&j_b[col + 1]);
#pragma unroll
            for (int half = 0; half < 2; half++) {
                int r = rowBase + wm + i * 16 + gr + half * 8;
                if (r >= cN) continue;
                int q0 = half * 2, q1 = half * 2 + 1;
                float2 o;
                o.x = sigmf(cg[i][j][q0] + ib0) * (cj[i][j][q0] + jb0);
                o.y = sigmf(cg[i][j][q1] + ib1) * (cj[i][j][q1] + jb1);
                *reinterpret_cast<float2*>(out + (size_t)r * cD + col) = o;
            }
        }
}

// ---------------- host ----------------
extern "C" void kernel_launch(void* const* d_in, const int* in_sizes, int n_in,
                              void* d_out, int out_size) {
    (void)in_sizes; (void)n_in; (void)out_size;
    const float* features = (const float*)d_in[0];
    const int*   src      = (const int*)d_in[1];
    const int*   dst      = (const int*)d_in[2];
    const int*   etypes   = (const int*)d_in[3];
    const float* W_et     = (const float*)d_in[4];
    const float* b_et     = (const float*)d_in[5];
    const float* W_ih     = (const float*)d_in[6];
    const float* b_ih     = (const float*)d_in[7];
    const float* W_hh     = (const float*)d_in[8];
    const float* b_hh     = (const float*)d_in[9];
    const float* i_w      = (const float*)d_in[10];
    const float* i_b      = (const float*)d_in[11];
    const float* j_w      = (const float*)d_in[12];
    const float* j_b      = (const float*)d_in[13];
    float* out = (float*)d_out;

    float *h0, *h1, *abuf;
    cudaGetSymbolAddress((void**)&h0, g_h0);
    cudaGetSymbolAddress((void**)&h1, g_h1);
    cudaGetSymbolAddress((void**)&abuf, g_a);

    cudaFuncSetAttribute(k_agg_etype, cudaFuncAttributeMaxDynamicSharedMemorySize, SM_AE);
    cudaFuncSetAttribute(k_gru_fused, cudaFuncAttributeMaxDynamicSharedMemorySize, SM_GRU);
    cudaFuncSetAttribute(k_head, cudaFuncAttributeMaxDynamicSharedMemorySize, SM_HEAD);

    // ---- CSR build (sorted by dst*4+etype) ----
    k_fill_deg<<<(cM + 255) / 256, 256>>>();
    k_hist<<<(cE + 255) / 256, 256>>>(dst, etypes);
    k_scan1<<<SCAN_NB, 1024>>>();
    k_scan2<<<1, 512>>>();
    k_scan3<<<SCAN_NB, 1024>>>();
    k_scatter<<<(cE + 255) / 256, 256>>>(src, dst, etypes);
    k_bsum<<<(cN * cD + 255) / 256, 256>>>(b_et);

    const int RB64 = (cN + 63) / 64;    // 1563
    const int RB128 = (cN + 127) / 128; // 782

    const float* hc = features;
    float* houts[3] = {h0, h1, h0};
    for (int s = 0; s < 3; s++) {
        k_agg_etype<<<RB64, 256, SM_AE>>>(hc, W_et);  // -> g_a
        k_gru_fused<<<dim3(RB128, 2), 256, SM_GRU>>>(abuf, hc, W_ih, b_ih, W_hh, b_hh, houts[s]);
        hc = houts[s];
    }
    k_head<<<RB128, 256, SM_HEAD>>>(hc, features, i_w, i_b, j_w, j_b, out);
}